// round 12
// baseline (speedup 1.0000x reference)
#include <cuda_runtime.h>
#include <cuda_fp16.h>
#include <cstdint>

#define HF 128
#define HV 32           // float4 per feature row
#define NMAX 50048
#define EMAX 800032

// ---------------- scratch (static device memory; no allocation) ----------------
__device__ float g_hn[NMAX * HF];        // relu(BN(x))
__device__ float g_u [NMAX * HF];        // agg + hn  (MLP input)
__device__ int   g_cnt[NMAX];
__device__ int   g_rs [NMAX + 1];
__device__ int   g_cur[NMAX];
__device__ int2  g_edges[EMAX];
// fragment-ordered fp16 weight images, 64KB each
__device__ uint2 g_w1h[8192];
__device__ uint2 g_w2h[8192];

// ---------------- helpers ----------------
__device__ __forceinline__ uint32_t pack2h(float a, float b) {
    __half2 h = __floats2half2_rn(a, b);
    return *reinterpret_cast<uint32_t*>(&h);
}

// f16 inputs, f32 accum
__device__ __forceinline__ void mma_f32acc(float* d, const uint32_t* a, uint32_t b0, uint32_t b1) {
    asm volatile(
        "mma.sync.aligned.m16n8k16.row.col.f32.f16.f16.f32 "
        "{%0,%1,%2,%3}, {%4,%5,%6,%7}, {%8,%9}, {%0,%1,%2,%3};"
        : "+f"(d[0]), "+f"(d[1]), "+f"(d[2]), "+f"(d[3])
        : "r"(a[0]), "r"(a[1]), "r"(a[2]), "r"(a[3]), "r"(b0), "r"(b1));
}

// ---------------- K0: hn = relu(BN(h))  +  degree histogram ----------------
__global__ void k_hn_hist(const float4* __restrict__ h,
                          const float4* __restrict__ bw, const float4* __restrict__ bb,
                          const float4* __restrict__ bm, const float4* __restrict__ bv,
                          const int* __restrict__ dst, int n, int e)
{
    int i = blockIdx.x * blockDim.x + threadIdx.x;
    if (i < e) atomicAdd(&g_cnt[dst[i]], 1);
    if (i >= n * HV) return;
    int j = i & (HV - 1);
    float4 x = h[i];
    float4 w = bw[j], b = bb[j], m = bm[j], v = bv[j];
    float4 o;
    o.x = fmaxf((x.x - m.x) * rsqrtf(v.x + 1e-5f) * w.x + b.x, 0.f);
    o.y = fmaxf((x.y - m.y) * rsqrtf(v.y + 1e-5f) * w.y + b.y, 0.f);
    o.z = fmaxf((x.z - m.z) * rsqrtf(v.z + 1e-5f) * w.z + b.z, 0.f);
    o.w = fmaxf((x.w - m.w) * rsqrtf(v.w + 1e-5f) * w.w + b.w, 0.f);
    ((float4*)g_hn)[i] = o;
}

// ---------------- K1: coalesced exclusive scan (single block) ----------------
__global__ void k_scan(int n)
{
    __shared__ int wsum[32];
    __shared__ int s_carry;
    int tid = threadIdx.x, lane = tid & 31, wid = tid >> 5;
    if (tid == 0) s_carry = 0;
    __syncthreads();
    int nIter = (n + 1023) >> 10;
    for (int it = 0; it < nIter; ++it) {
        int idx = (it << 10) + tid;
        int v = (idx < n) ? g_cnt[idx] : 0;
        int x = v;
        #pragma unroll
        for (int o = 1; o < 32; o <<= 1) {
            int u = __shfl_up_sync(0xffffffffu, x, o);
            if (lane >= o) x += u;
        }
        if (lane == 31) wsum[wid] = x;
        __syncthreads();
        if (wid == 0) {
            int w = wsum[lane];
            #pragma unroll
            for (int o = 1; o < 32; o <<= 1) {
                int u = __shfl_up_sync(0xffffffffu, w, o);
                if (lane >= o) w += u;
            }
            wsum[lane] = w;
        }
        __syncthreads();
        int carry = s_carry;
        int excl = x - v + (wid > 0 ? wsum[wid - 1] : 0) + carry;
        if (idx < n) { g_rs[idx] = excl; g_cur[idx] = excl; g_cnt[idx] = 0; }
        __syncthreads();
        if (tid == 0) s_carry = carry + wsum[31];
        __syncthreads();
    }
    if (tid == 0) g_rs[n] = s_carry;
}

// ---------------- K2: scatter edges by dst ----------------
__global__ void k_scatter(const int* __restrict__ src, const int* __restrict__ dst, int e)
{
    int i = blockIdx.x * blockDim.x + threadIdx.x;
    if (i >= e) return;
    int d = dst[i];
    int s = src[i];
    int p = atomicAdd(&g_cur[d], 1);
    g_edges[p] = make_int2(s, i);
}

// ---------------- K3: one-pass softmax aggregation (warp per dst node) ----------------
#define EDGE_ACC(a, hv)                                               \
    {                                                                 \
        float m0 = fmaxf(a.x + hv.x, 0.f) + 1e-7f;                    \
        float m1 = fmaxf(a.y + hv.y, 0.f) + 1e-7f;                    \
        float m2 = fmaxf(a.z + hv.z, 0.f) + 1e-7f;                    \
        float m3 = fmaxf(a.w + hv.w, 0.f) + 1e-7f;                    \
        float e0 = __expf(m0 * t);                                    \
        float e1 = __expf(m1 * t);                                    \
        float e2 = __expf(m2 * t);                                    \
        float e3 = __expf(m3 * t);                                    \
        S.x += e0; P.x = fmaf(m0, e0, P.x);                           \
        S.y += e1; P.y = fmaf(m1, e1, P.y);                           \
        S.z += e2; P.z = fmaf(m2, e2, P.z);                           \
        S.w += e3; P.w = fmaf(m3, e3, P.w);                           \
    }

__global__ void __launch_bounds__(256) k_agg(const float4* __restrict__ ea,
                                             const float* __restrict__ tp, int n)
{
    int warp = (blockIdx.x * blockDim.x + threadIdx.x) >> 5;
    int lane = threadIdx.x & 31;
    if (warp >= n) return;
    float t = __ldg(tp);
    int s0 = g_rs[warp], s1 = g_rs[warp + 1];
    const float4* hn4 = (const float4*)g_hn;
    float4 S = make_float4(0.f, 0.f, 0.f, 0.f);
    float4 P = make_float4(0.f, 0.f, 0.f, 0.f);

    int i = s0;
    for (; i + 4 <= s1; i += 4) {
        int2 q0 = g_edges[i + 0];
        int2 q1 = g_edges[i + 1];
        int2 q2 = g_edges[i + 2];
        int2 q3 = g_edges[i + 3];
        float4 a0 = ea [(size_t)q0.y * HV + lane];
        float4 h0 = hn4[(size_t)q0.x * HV + lane];
        float4 a1 = ea [(size_t)q1.y * HV + lane];
        float4 h1 = hn4[(size_t)q1.x * HV + lane];
        float4 a2 = ea [(size_t)q2.y * HV + lane];
        float4 h2 = hn4[(size_t)q2.x * HV + lane];
        float4 a3 = ea [(size_t)q3.y * HV + lane];
        float4 h3 = hn4[(size_t)q3.x * HV + lane];
        EDGE_ACC(a0, h0);
        EDGE_ACC(a1, h1);
        EDGE_ACC(a2, h2);
        EDGE_ACC(a3, h3);
    }
    for (; i < s1; ++i) {
        int2 q = g_edges[i];
        float4 a  = ea [(size_t)q.y * HV + lane];
        float4 hv = hn4[(size_t)q.x * HV + lane];
        EDGE_ACC(a, hv);
    }

    float4 hd = hn4[warp * HV + lane];
    float4 u;
    u.x = P.x / (S.x + 1e-16f) + hd.x;
    u.y = P.y / (S.y + 1e-16f) + hd.y;
    u.z = P.z / (S.z + 1e-16f) + hd.z;
    u.w = P.w / (S.w + 1e-16f) + hd.w;
    ((float4*)g_u)[warp * HV + lane] = u;
}

// ---------------- K4: prep fragment-ordered fp16 weight images ----------------
// W1: idx = ks(8)*1024 + nb(32)*32 + lane.  W2: idx = ks(16)*512 + nb(16)*32 + lane.
__global__ void k_prepw(const float* __restrict__ W1, const float* __restrict__ W2)
{
    int idx = blockIdx.x * blockDim.x + threadIdx.x;
    if (idx >= 16384) return;
    const float* W;
    uint2* ih;
    int ks, nb, l, ldn;
    if (idx < 8192) {
        int j = idx;
        ks = j >> 10; nb = (j >> 5) & 31; l = j & 31;
        W = W1; ih = g_w1h; ldn = 256;
    } else {
        int j = idx - 8192;
        ks = j >> 9; nb = (j >> 5) & 15; l = j & 31;
        W = W2; ih = g_w2h; ldn = 128;
    }
    int k0 = ks * 16 + (l & 3) * 2;
    int nn = nb * 8 + (l >> 2);
    float x00 = W[(size_t)(k0 + 0) * ldn + nn];
    float x01 = W[(size_t)(k0 + 1) * ldn + nn];
    float x10 = W[(size_t)(k0 + 8) * ldn + nn];
    float x11 = W[(size_t)(k0 + 9) * ldn + nn];
    ih[idx & 8191] = make_uint2(pack2h(x00, x01), pack2h(x10, x11));
}

// ---------------- K5: fused MLP  out = relu(LN(u@W1+b1)) @ W2 + b2 + h ----------------
// One kernel, warp-per-16-row-strip, y1 lives entirely in registers.
// GEMM1 D-fragment layout == GEMM2 A-fragment layout (nb = 2ks, 2ks+1).
#define SMEM_MLPF (131072 + 3584)
__global__ void __launch_bounds__(256) k_mlpf(const float* __restrict__ b1,
                                              const float* __restrict__ lnw,
                                              const float* __restrict__ lnb,
                                              const float* __restrict__ b2,
                                              const float* __restrict__ hres,
                                              float* __restrict__ out,
                                              int n, int nstrips)
{
    extern __shared__ char smem[];
    uint2* sW1   = (uint2*)smem;                     // 8192 (64KB)
    uint2* sW2   = (uint2*)(smem + 65536);           // 8192 (64KB)
    float* s_b1  = (float*)(smem + 131072);          // 256
    float* s_lnw = (float*)(smem + 131072 + 1024);   // 256
    float* s_lnb = (float*)(smem + 131072 + 2048);   // 256
    float* s_b2  = (float*)(smem + 131072 + 3072);   // 128
    int tid = threadIdx.x, wid = tid >> 5, lane = tid & 31;

    for (int i = tid; i < 8192; i += 256) { sW1[i] = g_w1h[i]; sW2[i] = g_w2h[i]; }
    if (tid < 256) { s_b1[tid] = b1[tid]; s_lnw[tid] = lnw[tid]; s_lnb[tid] = lnb[tid]; }
    if (tid < 128) s_b2[tid] = b2[tid];
    __syncthreads();

    int g = lane >> 2, t = lane & 3;
    int nwarps = gridDim.x * 8;

    for (int strip = blockIdx.x * 8 + wid; strip < nstrips; strip += nwarps) {
        int rg0 = strip * 16 + g;
        int rg1 = rg0 + 8;
        const float* up0 = g_u + (size_t)rg0 * 128;
        const float* up1 = g_u + (size_t)rg1 * 128;

        // ---- GEMM1: acc1[nb] covers y1 cols nb*8+2t..+1, rows rg0 / rg1; init with b1 ----
        float acc1[32][4];
        #pragma unroll
        for (int nb = 0; nb < 32; ++nb) {
            float bx = s_b1[nb * 8 + t * 2];
            float by = s_b1[nb * 8 + t * 2 + 1];
            acc1[nb][0] = bx; acc1[nb][1] = by;
            acc1[nb][2] = bx; acc1[nb][3] = by;
        }
        #pragma unroll
        for (int ks = 0; ks < 8; ++ks) {
            int k0 = ks * 16 + t * 2;
            float2 v00 = *(const float2*)(up0 + k0);
            float2 v01 = *(const float2*)(up0 + k0 + 8);
            float2 v10 = *(const float2*)(up1 + k0);
            float2 v11 = *(const float2*)(up1 + k0 + 8);
            uint32_t ah[4];
            ah[0] = pack2h(v00.x, v00.y);
            ah[1] = pack2h(v10.x, v10.y);
            ah[2] = pack2h(v01.x, v01.y);
            ah[3] = pack2h(v11.x, v11.y);
            const uint2* wh = sW1 + ks * 1024 + lane;
            #pragma unroll
            for (int nb = 0; nb < 32; ++nb) {
                uint2 bh = wh[nb * 32];
                mma_f32acc(acc1[nb], ah, bh.x, bh.y);
            }
        }

        // ---- LN stats: rows rg0 (vals [0],[1]) and rg1 ([2],[3]); quad-reduce over t ----
        float sA = 0.f, s2A = 0.f, sB = 0.f, s2B = 0.f;
        #pragma unroll
        for (int nb = 0; nb < 32; ++nb) {
            sA += acc1[nb][0] + acc1[nb][1];
            s2A = fmaf(acc1[nb][0], acc1[nb][0], fmaf(acc1[nb][1], acc1[nb][1], s2A));
            sB += acc1[nb][2] + acc1[nb][3];
            s2B = fmaf(acc1[nb][2], acc1[nb][2], fmaf(acc1[nb][3], acc1[nb][3], s2B));
        }
        #pragma unroll
        for (int o = 1; o < 4; o <<= 1) {
            sA  += __shfl_xor_sync(0xffffffffu, sA, o);
            s2A += __shfl_xor_sync(0xffffffffu, s2A, o);
            sB  += __shfl_xor_sync(0xffffffffu, sB, o);
            s2B += __shfl_xor_sync(0xffffffffu, s2B, o);
        }
        float meanA = sA * (1.f / 256.f);
        float varA  = fmaxf(s2A * (1.f / 256.f) - meanA * meanA, 0.f);
        float scaleA = rsqrtf(varA + 1e-5f);
        float meanB = sB * (1.f / 256.f);
        float varB  = fmaxf(s2B * (1.f / 256.f) - meanB * meanB, 0.f);
        float scaleB = rsqrtf(varB + 1e-5f);

        // ---- LN + relu + pack: acc1 -> GEMM2 A-fragments (afrag[ks*4..]) ----
        uint32_t afrag[64];
        #pragma unroll
        for (int ks = 0; ks < 16; ++ks) {
            int nb0 = 2 * ks, nb1 = 2 * ks + 1;
            int c0 = nb0 * 8 + t * 2;
            int c2 = nb1 * 8 + t * 2;
            float2 w0 = *(const float2*)(s_lnw + c0);
            float2 z0 = *(const float2*)(s_lnb + c0);
            float2 w1 = *(const float2*)(s_lnw + c2);
            float2 z1 = *(const float2*)(s_lnb + c2);
            float x00 = fmaxf((acc1[nb0][0] - meanA) * scaleA * w0.x + z0.x, 0.f);
            float x01 = fmaxf((acc1[nb0][1] - meanA) * scaleA * w0.y + z0.y, 0.f);
            float x10 = fmaxf((acc1[nb0][2] - meanB) * scaleB * w0.x + z0.x, 0.f);
            float x11 = fmaxf((acc1[nb0][3] - meanB) * scaleB * w0.y + z0.y, 0.f);
            float x02 = fmaxf((acc1[nb1][0] - meanA) * scaleA * w1.x + z1.x, 0.f);
            float x03 = fmaxf((acc1[nb1][1] - meanA) * scaleA * w1.y + z1.y, 0.f);
            float x12 = fmaxf((acc1[nb1][2] - meanB) * scaleB * w1.x + z1.x, 0.f);
            float x13 = fmaxf((acc1[nb1][3] - meanB) * scaleB * w1.y + z1.y, 0.f);
            afrag[ks * 4 + 0] = pack2h(x00, x01);   // row g,   k = 16ks+2t
            afrag[ks * 4 + 1] = pack2h(x10, x11);   // row g+8, k = 16ks+2t
            afrag[ks * 4 + 2] = pack2h(x02, x03);   // row g,   k = 16ks+8+2t
            afrag[ks * 4 + 3] = pack2h(x12, x13);   // row g+8, k = 16ks+8+2t
        }

        // ---- GEMM2: out cols nb2*8+2t..+1 ----
        float acc2[16][4];
        #pragma unroll
        for (int nb = 0; nb < 16; ++nb) {
            acc2[nb][0] = 0.f; acc2[nb][1] = 0.f; acc2[nb][2] = 0.f; acc2[nb][3] = 0.f;
        }
        #pragma unroll
        for (int ks = 0; ks < 16; ++ks) {
            const uint2* wh = sW2 + ks * 512 + lane;
            #pragma unroll
            for (int nb = 0; nb < 16; ++nb) {
                uint2 bh = wh[nb * 32];
                mma_f32acc(acc2[nb], afrag + ks * 4, bh.x, bh.y);
            }
        }

        // ---- epilogue: out = acc2 + b2 + h ----
        #pragma unroll
        for (int nb = 0; nb < 16; ++nb) {
            int col = nb * 8 + t * 2;
            float2 bb = *(const float2*)(s_b2 + col);
            if (rg0 < n) {
                float2 hv = *(const float2*)(hres + (size_t)rg0 * 128 + col);
                *(float2*)(out + (size_t)rg0 * 128 + col) =
                    make_float2(acc2[nb][0] + bb.x + hv.x, acc2[nb][1] + bb.y + hv.y);
            }
            if (rg1 < n) {
                float2 hv = *(const float2*)(hres + (size_t)rg1 * 128 + col);
                *(float2*)(out + (size_t)rg1 * 128 + col) =
                    make_float2(acc2[nb][2] + bb.x + hv.x, acc2[nb][3] + bb.y + hv.y);
            }
        }
    }
}

// ---------------- launch ----------------
extern "C" void kernel_launch(void* const* d_in, const int* in_sizes, int n_in,
                              void* d_out, int out_size)
{
    const float* h   = (const float*)d_in[0];
    const int*   ei  = (const int*)  d_in[1];
    const float* ea  = (const float*)d_in[2];
    const float* bw  = (const float*)d_in[3];
    const float* bb  = (const float*)d_in[4];
    const float* bm  = (const float*)d_in[5];
    const float* bv  = (const float*)d_in[6];
    const float* tp  = (const float*)d_in[7];
    const float* W1  = (const float*)d_in[8];
    const float* b1  = (const float*)d_in[9];
    const float* lnw = (const float*)d_in[10];
    const float* lnb = (const float*)d_in[11];
    const float* W2  = (const float*)d_in[12];
    const float* b2  = (const float*)d_in[13];

    int n = in_sizes[0] / HF;
    int e = in_sizes[2] / HF;
    const int* src = ei;
    const int* dst = ei + e;
    int nstrips = (n + 15) / 16;

    cudaFuncSetAttribute(k_mlpf, cudaFuncAttributeMaxDynamicSharedMemorySize, SMEM_MLPF);

    k_hn_hist<<<(n * HV + 255) / 256, 256>>>((const float4*)h, (const float4*)bw,
                                             (const float4*)bb, (const float4*)bm,
                                             (const float4*)bv, dst, n, e);
    k_scan<<<1, 1024>>>(n);
    k_scatter<<<(e + 255) / 256, 256>>>(src, dst, e);
    k_agg<<<(n + 7) / 8, 256>>>((const float4*)ea, tp, n);      // <- ncu capture lands here
    k_prepw<<<64, 256>>>(W1, W2);
    k_mlpf<<<152, 256, SMEM_MLPF>>>(b1, lnw, lnb, b2, h, (float*)d_out, n, nstrips);
}

// round 13
// speedup vs baseline: 1.1444x; 1.1444x over previous
#include <cuda_runtime.h>
#include <cuda_fp16.h>
#include <cstdint>

#define HF 128
#define HV 32           // float4 per feature row
#define NMAX 50048
#define EMAX 800032

// ---------------- scratch (static device memory; no allocation) ----------------
__device__ float g_hn[NMAX * HF];        // relu(BN(x))
__device__ float g_u [NMAX * HF];        // agg + hn  (MLP input)
__device__ float g_y1[NMAX * 2 * HF];    // GEMM1 output (pre-LN), L2-resident
__device__ float2 g_lnstat[NMAX];        // per-row (sum, sumsq) of y1, built by k_mma1
__device__ int   g_cnt[NMAX];
__device__ int   g_rs [NMAX + 1];
__device__ int   g_cur[NMAX];
__device__ int2  g_edges[EMAX];
// fragment-ordered fp16 weight images, 64KB each
__device__ uint2 g_w1h[8192];
__device__ uint2 g_w2h[8192];

// ---------------- helpers ----------------
__device__ __forceinline__ uint32_t pack2h(float a, float b) {
    __half2 h = __floats2half2_rn(a, b);
    return *reinterpret_cast<uint32_t*>(&h);
}

// f16 inputs, f32 accum
__device__ __forceinline__ void mma_f32acc(float* d, const uint32_t* a, uint32_t b0, uint32_t b1) {
    asm volatile(
        "mma.sync.aligned.m16n8k16.row.col.f32.f16.f16.f32 "
        "{%0,%1,%2,%3}, {%4,%5,%6,%7}, {%8,%9}, {%0,%1,%2,%3};"
        : "+f"(d[0]), "+f"(d[1]), "+f"(d[2]), "+f"(d[3])
        : "r"(a[0]), "r"(a[1]), "r"(a[2]), "r"(a[3]), "r"(b0), "r"(b1));
}

// ---------------- K0: hn = relu(BN(h)) + degree histogram + zero LN stats ----------------
__global__ void k_hn_hist(const float4* __restrict__ h,
                          const float4* __restrict__ bw, const float4* __restrict__ bb,
                          const float4* __restrict__ bm, const float4* __restrict__ bv,
                          const int* __restrict__ dst, int n, int e)
{
    int i = blockIdx.x * blockDim.x + threadIdx.x;
    if (i < e) atomicAdd(&g_cnt[dst[i]], 1);
    if (i < n) g_lnstat[i] = make_float2(0.f, 0.f);
    if (i >= n * HV) return;
    int j = i & (HV - 1);
    float4 x = h[i];
    float4 w = bw[j], b = bb[j], m = bm[j], v = bv[j];
    float4 o;
    o.x = fmaxf((x.x - m.x) * rsqrtf(v.x + 1e-5f) * w.x + b.x, 0.f);
    o.y = fmaxf((x.y - m.y) * rsqrtf(v.y + 1e-5f) * w.y + b.y, 0.f);
    o.z = fmaxf((x.z - m.z) * rsqrtf(v.z + 1e-5f) * w.z + b.z, 0.f);
    o.w = fmaxf((x.w - m.w) * rsqrtf(v.w + 1e-5f) * w.w + b.w, 0.f);
    ((float4*)g_hn)[i] = o;
}

// ---------------- K1: coalesced exclusive scan (single block) ----------------
__global__ void k_scan(int n)
{
    __shared__ int wsum[32];
    __shared__ int s_carry;
    int tid = threadIdx.x, lane = tid & 31, wid = tid >> 5;
    if (tid == 0) s_carry = 0;
    __syncthreads();
    int nIter = (n + 1023) >> 10;
    for (int it = 0; it < nIter; ++it) {
        int idx = (it << 10) + tid;
        int v = (idx < n) ? g_cnt[idx] : 0;
        int x = v;
        #pragma unroll
        for (int o = 1; o < 32; o <<= 1) {
            int u = __shfl_up_sync(0xffffffffu, x, o);
            if (lane >= o) x += u;
        }
        if (lane == 31) wsum[wid] = x;
        __syncthreads();
        if (wid == 0) {
            int w = wsum[lane];
            #pragma unroll
            for (int o = 1; o < 32; o <<= 1) {
                int u = __shfl_up_sync(0xffffffffu, w, o);
                if (lane >= o) w += u;
            }
            wsum[lane] = w;
        }
        __syncthreads();
        int carry = s_carry;
        int excl = x - v + (wid > 0 ? wsum[wid - 1] : 0) + carry;
        if (idx < n) { g_rs[idx] = excl; g_cur[idx] = excl; g_cnt[idx] = 0; }
        __syncthreads();
        if (tid == 0) s_carry = carry + wsum[31];
        __syncthreads();
    }
    if (tid == 0) g_rs[n] = s_carry;
}

// ---------------- K2: scatter edges by dst ----------------
__global__ void k_scatter(const int* __restrict__ src, const int* __restrict__ dst, int e)
{
    int i = blockIdx.x * blockDim.x + threadIdx.x;
    if (i >= e) return;
    int d = dst[i];
    int s = src[i];
    int p = atomicAdd(&g_cur[d], 1);
    g_edges[p] = make_int2(s, i);
}

// ---------------- K3: one-pass softmax aggregation (warp per dst node) ----------------
#define EDGE_ACC(a, hv)                                               \
    {                                                                 \
        float m0 = fmaxf(a.x + hv.x, 0.f) + 1e-7f;                    \
        float m1 = fmaxf(a.y + hv.y, 0.f) + 1e-7f;                    \
        float m2 = fmaxf(a.z + hv.z, 0.f) + 1e-7f;                    \
        float m3 = fmaxf(a.w + hv.w, 0.f) + 1e-7f;                    \
        float e0 = __expf(m0 * t);                                    \
        float e1 = __expf(m1 * t);                                    \
        float e2 = __expf(m2 * t);                                    \
        float e3 = __expf(m3 * t);                                    \
        S.x += e0; P.x = fmaf(m0, e0, P.x);                           \
        S.y += e1; P.y = fmaf(m1, e1, P.y);                           \
        S.z += e2; P.z = fmaf(m2, e2, P.z);                           \
        S.w += e3; P.w = fmaf(m3, e3, P.w);                           \
    }

__global__ void __launch_bounds__(256) k_agg(const float4* __restrict__ ea,
                                             const float* __restrict__ tp, int n)
{
    int warp = (blockIdx.x * blockDim.x + threadIdx.x) >> 5;
    int lane = threadIdx.x & 31;
    if (warp >= n) return;
    float t = __ldg(tp);
    int s0 = g_rs[warp], s1 = g_rs[warp + 1];
    const float4* hn4 = (const float4*)g_hn;
    float4 S = make_float4(0.f, 0.f, 0.f, 0.f);
    float4 P = make_float4(0.f, 0.f, 0.f, 0.f);

    int i = s0;
    for (; i + 4 <= s1; i += 4) {
        int2 q0 = g_edges[i + 0];
        int2 q1 = g_edges[i + 1];
        int2 q2 = g_edges[i + 2];
        int2 q3 = g_edges[i + 3];
        float4 a0 = ea [(size_t)q0.y * HV + lane];
        float4 h0 = hn4[(size_t)q0.x * HV + lane];
        float4 a1 = ea [(size_t)q1.y * HV + lane];
        float4 h1 = hn4[(size_t)q1.x * HV + lane];
        float4 a2 = ea [(size_t)q2.y * HV + lane];
        float4 h2 = hn4[(size_t)q2.x * HV + lane];
        float4 a3 = ea [(size_t)q3.y * HV + lane];
        float4 h3 = hn4[(size_t)q3.x * HV + lane];
        EDGE_ACC(a0, h0);
        EDGE_ACC(a1, h1);
        EDGE_ACC(a2, h2);
        EDGE_ACC(a3, h3);
    }
    for (; i < s1; ++i) {
        int2 q = g_edges[i];
        float4 a  = ea [(size_t)q.y * HV + lane];
        float4 hv = hn4[(size_t)q.x * HV + lane];
        EDGE_ACC(a, hv);
    }

    float4 hd = hn4[warp * HV + lane];
    float4 u;
    u.x = P.x / (S.x + 1e-16f) + hd.x;
    u.y = P.y / (S.y + 1e-16f) + hd.y;
    u.z = P.z / (S.z + 1e-16f) + hd.z;
    u.w = P.w / (S.w + 1e-16f) + hd.w;
    ((float4*)g_u)[warp * HV + lane] = u;
}

// ---------------- K4: prep fragment-ordered fp16 weight images ----------------
// W1: idx = ks(8)*1024 + nb(32)*32 + lane.  W2: idx = ks(16)*512 + nb(16)*32 + lane.
__global__ void k_prepw(const float* __restrict__ W1, const float* __restrict__ W2)
{
    int idx = blockIdx.x * blockDim.x + threadIdx.x;
    if (idx >= 16384) return;
    const float* W;
    uint2* ih;
    int ks, nb, l, ldn;
    if (idx < 8192) {
        int j = idx;
        ks = j >> 10; nb = (j >> 5) & 31; l = j & 31;
        W = W1; ih = g_w1h; ldn = 256;
    } else {
        int j = idx - 8192;
        ks = j >> 9; nb = (j >> 5) & 15; l = j & 31;
        W = W2; ih = g_w2h; ldn = 128;
    }
    int k0 = ks * 16 + (l & 3) * 2;
    int nn = nb * 8 + (l >> 2);
    float x00 = W[(size_t)(k0 + 0) * ldn + nn];
    float x01 = W[(size_t)(k0 + 1) * ldn + nn];
    float x10 = W[(size_t)(k0 + 8) * ldn + nn];
    float x11 = W[(size_t)(k0 + 9) * ldn + nn];
    ih[idx & 8191] = make_uint2(pack2h(x00, x01), pack2h(x10, x11));
}

// ---------------- K5: GEMM1 via mma.sync  y1 = u @ W1 + b1  (+ LN stat atomics) ----------------
// 304 CTAs = 2/SM; CTA owns a 128-col half (32KB weights); b1 folded into acc init.
#define SMEM_MMA1 (32768 + 512)
__global__ void __launch_bounds__(256, 2) k_mma1(const float* __restrict__ b1,
                                                 int n, int nstrips)
{
    extern __shared__ char smem[];
    uint2* sWh  = (uint2*)smem;             // 4096 (32KB): 8 ks x 16 nb x 32 lanes
    float* s_b1 = (float*)(smem + 32768);   // 128
    int tid = threadIdx.x, wid = tid >> 5, lane = tid & 31;
    int half = blockIdx.x & 1, slot = blockIdx.x >> 1;

    for (int i = tid; i < 4096; i += 256) {
        int ks = i >> 9, rem = i & 511;                 // ks in [0,8), rem = nb*32+lane
        sWh[i] = g_w1h[ks * 1024 + half * 512 + rem];
    }
    if (tid < 128) s_b1[tid] = b1[half * 128 + tid];
    __syncthreads();

    int g = lane >> 2, t = lane & 3;
    int nwarps = 152 * 8;
    for (int strip = slot * 8 + wid; strip < nstrips; strip += nwarps) {
        int rg0 = strip * 16 + g;
        int rg1 = rg0 + 8;
        const float* up0 = g_u + (size_t)rg0 * 128;
        const float* up1 = g_u + (size_t)rg1 * 128;
        float acc[16][4];
        #pragma unroll
        for (int nb = 0; nb < 16; ++nb) {
            float bx = s_b1[nb * 8 + t * 2];
            float by = s_b1[nb * 8 + t * 2 + 1];
            acc[nb][0] = bx; acc[nb][1] = by;
            acc[nb][2] = bx; acc[nb][3] = by;
        }
        #pragma unroll
        for (int ks = 0; ks < 8; ++ks) {
            int k0 = ks * 16 + t * 2;
            float2 v00 = *(const float2*)(up0 + k0);
            float2 v01 = *(const float2*)(up0 + k0 + 8);
            float2 v10 = *(const float2*)(up1 + k0);
            float2 v11 = *(const float2*)(up1 + k0 + 8);
            uint32_t ah[4];
            ah[0] = pack2h(v00.x, v00.y);
            ah[1] = pack2h(v10.x, v10.y);
            ah[2] = pack2h(v01.x, v01.y);
            ah[3] = pack2h(v11.x, v11.y);
            const uint2* wh = sWh + ks * 512 + lane;
            #pragma unroll
            for (int nb = 0; nb < 16; ++nb) {
                uint2 bh = wh[nb * 32];
                mma_f32acc(acc[nb], ah, bh.x, bh.y);
            }
        }

        // ---- LN partial stats over this half's 128 cols; quad-reduce; 2 atomics/row ----
        float sA = 0.f, s2A = 0.f, sB = 0.f, s2B = 0.f;
        #pragma unroll
        for (int nb = 0; nb < 16; ++nb) {
            sA += acc[nb][0] + acc[nb][1];
            s2A = fmaf(acc[nb][0], acc[nb][0], fmaf(acc[nb][1], acc[nb][1], s2A));
            sB += acc[nb][2] + acc[nb][3];
            s2B = fmaf(acc[nb][2], acc[nb][2], fmaf(acc[nb][3], acc[nb][3], s2B));
        }
        #pragma unroll
        for (int o = 1; o < 4; o <<= 1) {
            sA  += __shfl_xor_sync(0xffffffffu, sA, o);
            s2A += __shfl_xor_sync(0xffffffffu, s2A, o);
            sB  += __shfl_xor_sync(0xffffffffu, sB, o);
            s2B += __shfl_xor_sync(0xffffffffu, s2B, o);
        }
        if (t == 0) {
            if (rg0 < n) {
                atomicAdd(&g_lnstat[rg0].x, sA);
                atomicAdd(&g_lnstat[rg0].y, s2A);
            }
            if (rg1 < n) {
                atomicAdd(&g_lnstat[rg1].x, sB);
                atomicAdd(&g_lnstat[rg1].y, s2B);
            }
        }

        #pragma unroll
        for (int nb = 0; nb < 16; ++nb) {
            int col = half * 128 + nb * 8 + t * 2;
            if (rg0 < n)
                *(float2*)(g_y1 + (size_t)rg0 * 256 + col) =
                    make_float2(acc[nb][0], acc[nb][1]);
            if (rg1 < n)
                *(float2*)(g_y1 + (size_t)rg1 * 256 + col) =
                    make_float2(acc[nb][2], acc[nb][3]);
        }
    }
}

// ---------------- K6: GEMM2 via mma.sync  out = relu(LN(y1)) @ W2 + b2 + h ----------------
// 304 CTAs = 2/SM; CTA owns a 64-col half; LN mean/scale from precomputed g_lnstat.
#define SMEM_MMA2 (32768 + 2304)
__global__ void __launch_bounds__(256, 2) k_mma2(const float* __restrict__ b2,
                                                 const float* __restrict__ lnw,
                                                 const float* __restrict__ lnb,
                                                 const float* __restrict__ hres,
                                                 float* __restrict__ out,
                                                 int n, int nstrips)
{
    extern __shared__ char smem[];
    uint2* sWh   = (uint2*)smem;                     // 4096 (32KB): 16 ks x 8 nb x 32 lanes
    float* s_lnw = (float*)(smem + 32768);           // 256
    float* s_lnb = (float*)(smem + 32768 + 1024);    // 256
    float* s_b2  = (float*)(smem + 32768 + 2048);    // 64
    int tid = threadIdx.x, wid = tid >> 5, lane = tid & 31;
    int half = blockIdx.x & 1, slot = blockIdx.x >> 1;

    for (int i = tid; i < 4096; i += 256) {
        int ks = i >> 8, rem = i & 255;                 // ks in [0,16), rem = nb*32+lane
        sWh[i] = g_w2h[ks * 512 + half * 256 + rem];
    }
    if (tid < 256) { s_lnw[tid] = lnw[tid]; s_lnb[tid] = lnb[tid]; }
    if (tid < 64) s_b2[tid] = b2[half * 64 + tid];
    __syncthreads();

    int g = lane >> 2, t = lane & 3;
    int nwarps = 152 * 8;
    for (int strip = slot * 8 + wid; strip < nstrips; strip += nwarps) {
        int rg0 = strip * 16 + g, rg1 = rg0 + 8;

        // ---- LN mean/scale from precomputed stats (one float2 per row) ----
        float2 stA = (rg0 < n) ? g_lnstat[rg0] : make_float2(0.f, 0.f);
        float2 stB = (rg1 < n) ? g_lnstat[rg1] : make_float2(0.f, 0.f);
        float meanA = stA.x * (1.f / 256.f);
        float varA  = fmaxf(stA.y * (1.f / 256.f) - meanA * meanA, 0.f);
        float scaleA = rsqrtf(varA + 1e-5f);
        float meanB = stB.x * (1.f / 256.f);
        float varB  = fmaxf(stB.y * (1.f / 256.f) - meanB * meanB, 0.f);
        float scaleB = rsqrtf(varB + 1e-5f);

        const float* yp0 = g_y1 + (size_t)rg0 * 256;
        const float* yp1 = g_y1 + (size_t)rg1 * 256;
        float acc[8][4];
        #pragma unroll
        for (int nb = 0; nb < 8; ++nb) {
            acc[nb][0] = 0.f; acc[nb][1] = 0.f; acc[nb][2] = 0.f; acc[nb][3] = 0.f;
        }
        #pragma unroll
        for (int ks = 0; ks < 16; ++ks) {
            int k0 = ks * 16 + t * 2;
            float2 v00 = *(const float2*)(yp0 + k0);
            float2 v01 = *(const float2*)(yp0 + k0 + 8);
            float2 v10 = *(const float2*)(yp1 + k0);
            float2 v11 = *(const float2*)(yp1 + k0 + 8);
            float2 w0 = *(const float2*)(s_lnw + k0);
            float2 w1 = *(const float2*)(s_lnw + k0 + 8);
            float2 z0 = *(const float2*)(s_lnb + k0);
            float2 z1 = *(const float2*)(s_lnb + k0 + 8);
            float x00 = fmaxf((v00.x - meanA) * scaleA * w0.x + z0.x, 0.f);
            float x01 = fmaxf((v00.y - meanA) * scaleA * w0.y + z0.y, 0.f);
            float x02 = fmaxf((v01.x - meanA) * scaleA * w1.x + z1.x, 0.f);
            float x03 = fmaxf((v01.y - meanA) * scaleA * w1.y + z1.y, 0.f);
            float x10 = fmaxf((v10.x - meanB) * scaleB * w0.x + z0.x, 0.f);
            float x11 = fmaxf((v10.y - meanB) * scaleB * w0.y + z0.y, 0.f);
            float x12 = fmaxf((v11.x - meanB) * scaleB * w1.x + z1.x, 0.f);
            float x13 = fmaxf((v11.y - meanB) * scaleB * w1.y + z1.y, 0.f);
            uint32_t ah[4];
            ah[0] = pack2h(x00, x01);
            ah[1] = pack2h(x10, x11);
            ah[2] = pack2h(x02, x03);
            ah[3] = pack2h(x12, x13);
            const uint2* wh = sWh + ks * 256 + lane;
            #pragma unroll
            for (int nb = 0; nb < 8; ++nb) {
                uint2 bh = wh[nb * 32];
                mma_f32acc(acc[nb], ah, bh.x, bh.y);
            }
        }
        #pragma unroll
        for (int nb = 0; nb < 8; ++nb) {
            int col = half * 64 + nb * 8 + t * 2;
            float2 bb = *(const float2*)(s_b2 + nb * 8 + t * 2);
            if (rg0 < n) {
                float2 hv = *(const float2*)(hres + (size_t)rg0 * 128 + col);
                *(float2*)(out + (size_t)rg0 * 128 + col) =
                    make_float2(acc[nb][0] + bb.x + hv.x, acc[nb][1] + bb.y + hv.y);
            }
            if (rg1 < n) {
                float2 hv = *(const float2*)(hres + (size_t)rg1 * 128 + col);
                *(float2*)(out + (size_t)rg1 * 128 + col) =
                    make_float2(acc[nb][2] + bb.x + hv.x, acc[nb][3] + bb.y + hv.y);
            }
        }
    }
}

// ---------------- launch ----------------
extern "C" void kernel_launch(void* const* d_in, const int* in_sizes, int n_in,
                              void* d_out, int out_size)
{
    const float* h   = (const float*)d_in[0];
    const int*   ei  = (const int*)  d_in[1];
    const float* ea  = (const float*)d_in[2];
    const float* bw  = (const float*)d_in[3];
    const float* bb  = (const float*)d_in[4];
    const float* bm  = (const float*)d_in[5];
    const float* bv  = (const float*)d_in[6];
    const float* tp  = (const float*)d_in[7];
    const float* W1  = (const float*)d_in[8];
    const float* b1  = (const float*)d_in[9];
    const float* lnw = (const float*)d_in[10];
    const float* lnb = (const float*)d_in[11];
    const float* W2  = (const float*)d_in[12];
    const float* b2  = (const float*)d_in[13];

    int n = in_sizes[0] / HF;
    int e = in_sizes[2] / HF;
    const int* src = ei;
    const int* dst = ei + e;
    int nstrips = (n + 15) / 16;

    cudaFuncSetAttribute(k_mma1, cudaFuncAttributeMaxDynamicSharedMemorySize, SMEM_MMA1);
    cudaFuncSetAttribute(k_mma2, cudaFuncAttributeMaxDynamicSharedMemorySize, SMEM_MMA2);

    k_hn_hist<<<(n * HV + 255) / 256, 256>>>((const float4*)h, (const float4*)bw,
                                             (const float4*)bb, (const float4*)bm,
                                             (const float4*)bv, dst, n, e);
    k_scan<<<1, 1024>>>(n);
    k_scatter<<<(e + 255) / 256, 256>>>(src, dst, e);
    k_agg<<<(n + 7) / 8, 256>>>((const float4*)ea, tp, n);      // <- ncu capture lands here
    k_prepw<<<64, 256>>>(W1, W2);
    k_mma1<<<304, 256, SMEM_MMA1>>>(b1, n, nstrips);
    k_mma2<<<304, 256, SMEM_MMA2>>>(b2, lnw, lnb, h, (float*)d_out, n, nstrips);
}

// round 14
// speedup vs baseline: 1.2175x; 1.0639x over previous
#include <cuda_runtime.h>
#include <cuda_fp16.h>
#include <cstdint>

#define HF 128
#define HV 32           // float4 per feature row
#define NMAX 50048
#define EMAX 800032

// ---------------- scratch (static device memory; no allocation) ----------------
__device__ float    g_hn[NMAX * HF];     // relu(BN(x)), f32
__device__ uint32_t g_u [NMAX * 64];     // agg + hn, fp16 (half2-packed), MLP input
__device__ uint32_t g_y1[NMAX * 128];    // GEMM1 output (pre-LN), fp16 packed
__device__ float2   g_lnstat[NMAX];      // per-row (sum, sumsq) of y1, built by k_mma1
__device__ int   g_cnt[NMAX];
__device__ int   g_rs [NMAX + 1];
__device__ int   g_cur[NMAX];
__device__ int2  g_edges[EMAX];
// fragment-ordered fp16 weight images, 64KB each
__device__ uint2 g_w1h[8192];
__device__ uint2 g_w2h[8192];

// ---------------- helpers ----------------
__device__ __forceinline__ uint32_t pack2h(float a, float b) {
    __half2 h = __floats2half2_rn(a, b);
    return *reinterpret_cast<uint32_t*>(&h);
}
__device__ __forceinline__ float2 unpack2h(uint32_t v) {
    __half2 h = *reinterpret_cast<__half2*>(&v);
    return __half22float2(h);
}

// f16 inputs, f32 accum
__device__ __forceinline__ void mma_f32acc(float* d, const uint32_t* a, uint32_t b0, uint32_t b1) {
    asm volatile(
        "mma.sync.aligned.m16n8k16.row.col.f32.f16.f16.f32 "
        "{%0,%1,%2,%3}, {%4,%5,%6,%7}, {%8,%9}, {%0,%1,%2,%3};"
        : "+f"(d[0]), "+f"(d[1]), "+f"(d[2]), "+f"(d[3])
        : "r"(a[0]), "r"(a[1]), "r"(a[2]), "r"(a[3]), "r"(b0), "r"(b1));
}

// ---------------- K0: hn = relu(BN(h)) + degree histogram + zero LN stats ----------------
__global__ void k_hn_hist(const float4* __restrict__ h,
                          const float4* __restrict__ bw, const float4* __restrict__ bb,
                          const float4* __restrict__ bm, const float4* __restrict__ bv,
                          const int* __restrict__ dst, int n, int e)
{
    int i = blockIdx.x * blockDim.x + threadIdx.x;
    if (i < e) atomicAdd(&g_cnt[dst[i]], 1);
    if (i < n) g_lnstat[i] = make_float2(0.f, 0.f);
    if (i >= n * HV) return;
    int j = i & (HV - 1);
    float4 x = h[i];
    float4 w = bw[j], b = bb[j], m = bm[j], v = bv[j];
    float4 o;
    o.x = fmaxf((x.x - m.x) * rsqrtf(v.x + 1e-5f) * w.x + b.x, 0.f);
    o.y = fmaxf((x.y - m.y) * rsqrtf(v.y + 1e-5f) * w.y + b.y, 0.f);
    o.z = fmaxf((x.z - m.z) * rsqrtf(v.z + 1e-5f) * w.z + b.z, 0.f);
    o.w = fmaxf((x.w - m.w) * rsqrtf(v.w + 1e-5f) * w.w + b.w, 0.f);
    ((float4*)g_hn)[i] = o;
}

// ---------------- K1: pipelined exclusive scan (single block) ----------------
__global__ void k_scan(int n)
{
    __shared__ int wsum[32];
    __shared__ int s_carry;
    int tid = threadIdx.x, lane = tid & 31, wid = tid >> 5;
    if (tid == 0) s_carry = 0;
    int nIter = (n + 1023) >> 10;
    int idx = tid;
    int v = (idx < n) ? g_cnt[idx] : 0;      // prime the pipeline
    __syncthreads();
    for (int it = 0; it < nIter; ++it) {
        int nidx = idx + 1024;
        int vnext = (it + 1 < nIter && nidx < n) ? g_cnt[nidx] : 0;  // prefetch, hidden by scan
        int x = v;
        #pragma unroll
        for (int o = 1; o < 32; o <<= 1) {
            int u = __shfl_up_sync(0xffffffffu, x, o);
            if (lane >= o) x += u;
        }
        if (lane == 31) wsum[wid] = x;
        __syncthreads();
        if (wid == 0) {
            int w = wsum[lane];
            #pragma unroll
            for (int o = 1; o < 32; o <<= 1) {
                int u = __shfl_up_sync(0xffffffffu, w, o);
                if (lane >= o) w += u;
            }
            wsum[lane] = w;
        }
        __syncthreads();
        int carry = s_carry;
        int excl = x - v + (wid > 0 ? wsum[wid - 1] : 0) + carry;
        if (idx < n) { g_rs[idx] = excl; g_cur[idx] = excl; g_cnt[idx] = 0; }
        __syncthreads();
        if (tid == 0) s_carry = carry + wsum[31];
        __syncthreads();
        idx = nidx; v = vnext;
    }
    if (tid == 0) g_rs[n] = s_carry;
}

// ---------------- K2: scatter edges by dst ----------------
__global__ void k_scatter(const int* __restrict__ src, const int* __restrict__ dst, int e)
{
    int i = blockIdx.x * blockDim.x + threadIdx.x;
    if (i >= e) return;
    int d = dst[i];
    int s = src[i];
    int p = atomicAdd(&g_cur[d], 1);
    g_edges[p] = make_int2(s, i);
}

// ---------------- K3: one-pass softmax aggregation (warp per dst node) ----------------
#define EDGE_ACC(a, hv)                                               \
    {                                                                 \
        float m0 = fmaxf(a.x + hv.x, 0.f) + 1e-7f;                    \
        float m1 = fmaxf(a.y + hv.y, 0.f) + 1e-7f;                    \
        float m2 = fmaxf(a.z + hv.z, 0.f) + 1e-7f;                    \
        float m3 = fmaxf(a.w + hv.w, 0.f) + 1e-7f;                    \
        float e0 = __expf(m0 * t);                                    \
        float e1 = __expf(m1 * t);                                    \
        float e2 = __expf(m2 * t);                                    \
        float e3 = __expf(m3 * t);                                    \
        S.x += e0; P.x = fmaf(m0, e0, P.x);                           \
        S.y += e1; P.y = fmaf(m1, e1, P.y);                           \
        S.z += e2; P.z = fmaf(m2, e2, P.z);                           \
        S.w += e3; P.w = fmaf(m3, e3, P.w);                           \
    }

__global__ void __launch_bounds__(256) k_agg(const float4* __restrict__ ea,
                                             const float* __restrict__ tp, int n)
{
    int warp = (blockIdx.x * blockDim.x + threadIdx.x) >> 5;
    int lane = threadIdx.x & 31;
    if (warp >= n) return;
    float t = __ldg(tp);
    int s0 = g_rs[warp], s1 = g_rs[warp + 1];
    const float4* hn4 = (const float4*)g_hn;
    float4 S = make_float4(0.f, 0.f, 0.f, 0.f);
    float4 P = make_float4(0.f, 0.f, 0.f, 0.f);

    int i = s0;
    for (; i + 4 <= s1; i += 4) {
        int2 q0 = g_edges[i + 0];
        int2 q1 = g_edges[i + 1];
        int2 q2 = g_edges[i + 2];
        int2 q3 = g_edges[i + 3];
        float4 a0 = ea [(size_t)q0.y * HV + lane];
        float4 h0 = hn4[(size_t)q0.x * HV + lane];
        float4 a1 = ea [(size_t)q1.y * HV + lane];
        float4 h1 = hn4[(size_t)q1.x * HV + lane];
        float4 a2 = ea [(size_t)q2.y * HV + lane];
        float4 h2 = hn4[(size_t)q2.x * HV + lane];
        float4 a3 = ea [(size_t)q3.y * HV + lane];
        float4 h3 = hn4[(size_t)q3.x * HV + lane];
        EDGE_ACC(a0, h0);
        EDGE_ACC(a1, h1);
        EDGE_ACC(a2, h2);
        EDGE_ACC(a3, h3);
    }
    for (; i < s1; ++i) {
        int2 q = g_edges[i];
        float4 a  = ea [(size_t)q.y * HV + lane];
        float4 hv = hn4[(size_t)q.x * HV + lane];
        EDGE_ACC(a, hv);
    }

    float4 hd = hn4[warp * HV + lane];
    float ux = P.x / (S.x + 1e-16f) + hd.x;
    float uy = P.y / (S.y + 1e-16f) + hd.y;
    float uz = P.z / (S.z + 1e-16f) + hd.z;
    float uw = P.w / (S.w + 1e-16f) + hd.w;
    // write u as fp16 (identical rounding point to the old mma1 pack)
    ((uint2*)g_u)[warp * 32 + lane] = make_uint2(pack2h(ux, uy), pack2h(uz, uw));
}

// ---------------- K4: prep fragment-ordered fp16 weight images ----------------
// W1: idx = ks(8)*1024 + nb(32)*32 + lane.  W2: idx = ks(16)*512 + nb(16)*32 + lane.
__global__ void k_prepw(const float* __restrict__ W1, const float* __restrict__ W2)
{
    int idx = blockIdx.x * blockDim.x + threadIdx.x;
    if (idx >= 16384) return;
    const float* W;
    uint2* ih;
    int ks, nb, l, ldn;
    if (idx < 8192) {
        int j = idx;
        ks = j >> 10; nb = (j >> 5) & 31; l = j & 31;
        W = W1; ih = g_w1h; ldn = 256;
    } else {
        int j = idx - 8192;
        ks = j >> 9; nb = (j >> 5) & 15; l = j & 31;
        W = W2; ih = g_w2h; ldn = 128;
    }
    int k0 = ks * 16 + (l & 3) * 2;
    int nn = nb * 8 + (l >> 2);
    float x00 = W[(size_t)(k0 + 0) * ldn + nn];
    float x01 = W[(size_t)(k0 + 1) * ldn + nn];
    float x10 = W[(size_t)(k0 + 8) * ldn + nn];
    float x11 = W[(size_t)(k0 + 9) * ldn + nn];
    ih[idx & 8191] = make_uint2(pack2h(x00, x01), pack2h(x10, x11));
}

// ---------------- K5: GEMM1 via mma.sync  y1 = u @ W1 + b1  (+ LN stat atomics) ----------------
// 304 CTAs = 2/SM; CTA owns a 128-col half (32KB weights); u read as ready fp16 fragments.
#define SMEM_MMA1 (32768 + 512)
__global__ void __launch_bounds__(256, 2) k_mma1(const float* __restrict__ b1,
                                                 int n, int nstrips)
{
    extern __shared__ char smem[];
    uint2* sWh  = (uint2*)smem;             // 4096 (32KB): 8 ks x 16 nb x 32 lanes
    float* s_b1 = (float*)(smem + 32768);   // 128
    int tid = threadIdx.x, wid = tid >> 5, lane = tid & 31;
    int half = blockIdx.x & 1, slot = blockIdx.x >> 1;

    for (int i = tid; i < 4096; i += 256) {
        int ks = i >> 9, rem = i & 511;
        sWh[i] = g_w1h[ks * 1024 + half * 512 + rem];
    }
    if (tid < 128) s_b1[tid] = b1[half * 128 + tid];
    __syncthreads();

    int g = lane >> 2, t = lane & 3;
    int nwarps = 152 * 8;
    for (int strip = slot * 8 + wid; strip < nstrips; strip += nwarps) {
        int rg0 = strip * 16 + g;
        int rg1 = rg0 + 8;
        const uint32_t* u0 = g_u + (size_t)rg0 * 64;   // fp16 row: 64 uint32
        const uint32_t* u1 = g_u + (size_t)rg1 * 64;
        float acc[16][4];
        #pragma unroll
        for (int nb = 0; nb < 16; ++nb) {
            float bx = s_b1[nb * 8 + t * 2];
            float by = s_b1[nb * 8 + t * 2 + 1];
            acc[nb][0] = bx; acc[nb][1] = by;
            acc[nb][2] = bx; acc[nb][3] = by;
        }
        #pragma unroll
        for (int ks = 0; ks < 8; ++ks) {
            uint32_t ah[4];
            ah[0] = u0[ks * 8 + t];
            ah[1] = u1[ks * 8 + t];
            ah[2] = u0[ks * 8 + t + 4];
            ah[3] = u1[ks * 8 + t + 4];
            const uint2* wh = sWh + ks * 512 + lane;
            #pragma unroll
            for (int nb = 0; nb < 16; ++nb) {
                uint2 bh = wh[nb * 32];
                mma_f32acc(acc[nb], ah, bh.x, bh.y);
            }
        }

        // ---- LN partial stats over this half's 128 cols; quad-reduce; 2 atomics/row ----
        float sA = 0.f, s2A = 0.f, sB = 0.f, s2B = 0.f;
        #pragma unroll
        for (int nb = 0; nb < 16; ++nb) {
            sA += acc[nb][0] + acc[nb][1];
            s2A = fmaf(acc[nb][0], acc[nb][0], fmaf(acc[nb][1], acc[nb][1], s2A));
            sB += acc[nb][2] + acc[nb][3];
            s2B = fmaf(acc[nb][2], acc[nb][2], fmaf(acc[nb][3], acc[nb][3], s2B));
        }
        #pragma unroll
        for (int o = 1; o < 4; o <<= 1) {
            sA  += __shfl_xor_sync(0xffffffffu, sA, o);
            s2A += __shfl_xor_sync(0xffffffffu, s2A, o);
            sB  += __shfl_xor_sync(0xffffffffu, sB, o);
            s2B += __shfl_xor_sync(0xffffffffu, s2B, o);
        }
        if (t == 0) {
            if (rg0 < n) {
                atomicAdd(&g_lnstat[rg0].x, sA);
                atomicAdd(&g_lnstat[rg0].y, s2A);
            }
            if (rg1 < n) {
                atomicAdd(&g_lnstat[rg1].x, sB);
                atomicAdd(&g_lnstat[rg1].y, s2B);
            }
        }

        // ---- store y1 as fp16 (one uint32 per nb per row) ----
        #pragma unroll
        for (int nb = 0; nb < 16; ++nb) {
            int ci = half * 64 + nb * 4 + t;      // uint32 index within row of 128
            if (rg0 < n) g_y1[(size_t)rg0 * 128 + ci] = pack2h(acc[nb][0], acc[nb][1]);
            if (rg1 < n) g_y1[(size_t)rg1 * 128 + ci] = pack2h(acc[nb][2], acc[nb][3]);
        }
    }
}

// ---------------- K6: GEMM2 via mma.sync  out = relu(LN(y1)) @ W2 + b2 + h ----------------
// 304 CTAs = 2/SM; CTA owns a 64-col half; LN mean/scale from g_lnstat; y1 read as fp16.
#define SMEM_MMA2 (32768 + 2304)
__global__ void __launch_bounds__(256, 2) k_mma2(const float* __restrict__ b2,
                                                 const float* __restrict__ lnw,
                                                 const float* __restrict__ lnb,
                                                 const float* __restrict__ hres,
                                                 float* __restrict__ out,
                                                 int n, int nstrips)
{
    extern __shared__ char smem[];
    uint2* sWh   = (uint2*)smem;                     // 4096 (32KB): 16 ks x 8 nb x 32 lanes
    float* s_lnw = (float*)(smem + 32768);           // 256
    float* s_lnb = (float*)(smem + 32768 + 1024);    // 256
    float* s_b2  = (float*)(smem + 32768 + 2048);    // 64
    int tid = threadIdx.x, wid = tid >> 5, lane = tid & 31;
    int half = blockIdx.x & 1, slot = blockIdx.x >> 1;

    for (int i = tid; i < 4096; i += 256) {
        int ks = i >> 8, rem = i & 255;
        sWh[i] = g_w2h[ks * 512 + half * 256 + rem];
    }
    if (tid < 256) { s_lnw[tid] = lnw[tid]; s_lnb[tid] = lnb[tid]; }
    if (tid < 64) s_b2[tid] = b2[half * 64 + tid];
    __syncthreads();

    int g = lane >> 2, t = lane & 3;
    int nwarps = 152 * 8;
    for (int strip = slot * 8 + wid; strip < nstrips; strip += nwarps) {
        int rg0 = strip * 16 + g, rg1 = rg0 + 8;

        float2 stA = (rg0 < n) ? g_lnstat[rg0] : make_float2(0.f, 0.f);
        float2 stB = (rg1 < n) ? g_lnstat[rg1] : make_float2(0.f, 0.f);
        float meanA = stA.x * (1.f / 256.f);
        float varA  = fmaxf(stA.y * (1.f / 256.f) - meanA * meanA, 0.f);
        float scaleA = rsqrtf(varA + 1e-5f);
        float meanB = stB.x * (1.f / 256.f);
        float varB  = fmaxf(stB.y * (1.f / 256.f) - meanB * meanB, 0.f);
        float scaleB = rsqrtf(varB + 1e-5f);

        const uint32_t* y0 = g_y1 + (size_t)rg0 * 128;
        const uint32_t* y1 = g_y1 + (size_t)rg1 * 128;
        float acc[8][4];
        #pragma unroll
        for (int nb = 0; nb < 8; ++nb) {
            acc[nb][0] = 0.f; acc[nb][1] = 0.f; acc[nb][2] = 0.f; acc[nb][3] = 0.f;
        }
        #pragma unroll
        for (int ks = 0; ks < 16; ++ks) {
            int k0 = ks * 16 + t * 2;
            float2 v00 = unpack2h(y0[ks * 8 + t]);
            float2 v01 = unpack2h(y0[ks * 8 + t + 4]);
            float2 v10 = unpack2h(y1[ks * 8 + t]);
            float2 v11 = unpack2h(y1[ks * 8 + t + 4]);
            float2 w0 = *(const float2*)(s_lnw + k0);
            float2 w1 = *(const float2*)(s_lnw + k0 + 8);
            float2 z0 = *(const float2*)(s_lnb + k0);
            float2 z1 = *(const float2*)(s_lnb + k0 + 8);
            float x00 = fmaxf((v00.x - meanA) * scaleA * w0.x + z0.x, 0.f);
            float x01 = fmaxf((v00.y - meanA) * scaleA * w0.y + z0.y, 0.f);
            float x02 = fmaxf((v01.x - meanA) * scaleA * w1.x + z1.x, 0.f);
            float x03 = fmaxf((v01.y - meanA) * scaleA * w1.y + z1.y, 0.f);
            float x10 = fmaxf((v10.x - meanB) * scaleB * w0.x + z0.x, 0.f);
            float x11 = fmaxf((v10.y - meanB) * scaleB * w0.y + z0.y, 0.f);
            float x12 = fmaxf((v11.x - meanB) * scaleB * w1.x + z1.x, 0.f);
            float x13 = fmaxf((v11.y - meanB) * scaleB * w1.y + z1.y, 0.f);
            uint32_t ah[4];
            ah[0] = pack2h(x00, x01);
            ah[1] = pack2h(x10, x11);
            ah[2] = pack2h(x02, x03);
            ah[3] = pack2h(x12, x13);
            const uint2* wh = sWh + ks * 256 + lane;
            #pragma unroll
            for (int nb = 0; nb < 8; ++nb) {
                uint2 bh = wh[nb * 32];
                mma_f32acc(acc[nb], ah, bh.x, bh.y);
            }
        }
        #pragma unroll
        for (int nb = 0; nb < 8; ++nb) {
            int col = half * 64 + nb * 8 + t * 2;
            float2 bb = *(const float2*)(s_b2 + nb * 8 + t * 2);
            if (rg0 < n) {
                float2 hv = *(const float2*)(hres + (size_t)rg0 * 128 + col);
                *(float2*)(out + (size_t)rg0 * 128 + col) =
                    make_float2(acc[nb][0] + bb.x + hv.x, acc[nb][1] + bb.y + hv.y);
            }
            if (rg1 < n) {
                float2 hv = *(const float2*)(hres + (size_t)rg1 * 128 + col);
                *(float2*)(out + (size_t)rg1 * 128 + col) =
                    make_float2(acc[nb][2] + bb.x + hv.x, acc[nb][3] + bb.y + hv.y);
            }
        }
    }
}

// ---------------- launch ----------------
extern "C" void kernel_launch(void* const* d_in, const int* in_sizes, int n_in,
                              void* d_out, int out_size)
{
    const float* h   = (const float*)d_in[0];
    const int*   ei  = (const int*)  d_in[1];
    const float* ea  = (const float*)d_in[2];
    const float* bw  = (const float*)d_in[3];
    const float* bb  = (const float*)d_in[4];
    const float* bm  = (const float*)d_in[5];
    const float* bv  = (const float*)d_in[6];
    const float* tp  = (const float*)d_in[7];
    const float* W1  = (const float*)d_in[8];
    const float* b1  = (const float*)d_in[9];
    const float* lnw = (const float*)d_in[10];
    const float* lnb = (const float*)d_in[11];
    const float* W2  = (const float*)d_in[12];
    const float* b2  = (const float*)d_in[13];

    int n = in_sizes[0] / HF;
    int e = in_sizes[2] / HF;
    const int* src = ei;
    const int* dst = ei + e;
    int nstrips = (n + 15) / 16;

    cudaFuncSetAttribute(k_mma1, cudaFuncAttributeMaxDynamicSharedMemorySize, SMEM_MMA1);
    cudaFuncSetAttribute(k_mma2, cudaFuncAttributeMaxDynamicSharedMemorySize, SMEM_MMA2);

    k_hn_hist<<<(n * HV + 255) / 256, 256>>>((const float4*)h, (const float4*)bw,
                                             (const float4*)bb, (const float4*)bm,
                                             (const float4*)bv, dst, n, e);
    k_scan<<<1, 1024>>>(n);
    k_scatter<<<(e + 255) / 256, 256>>>(src, dst, e);
    k_agg<<<(n + 7) / 8, 256>>>((const float4*)ea, tp, n);      // <- ncu capture lands here
    k_prepw<<<64, 256>>>(W1, W2);
    k_mma1<<<304, 256, SMEM_MMA1>>>(b1, n, nstrips);
    k_mma2<<<304, 256, SMEM_MMA2>>>(b2, lnw, lnb, h, (float*)d_out, n, nstrips);
}

// round 15
// speedup vs baseline: 1.3043x; 1.0712x over previous
#include <cuda_runtime.h>
#include <cuda_fp16.h>
#include <cstdint>

#define HF 128
#define HV 32           // float4 per feature row
#define NMAX 50048
#define EMAX 800032

// ---------------- scratch (static device memory; no allocation) ----------------
__device__ float    g_hn[NMAX * HF];     // relu(BN(x)), f32
__device__ uint32_t g_u [NMAX * 64];     // agg + hn, fp16 (half2-packed), MLP input
__device__ uint32_t g_y1[NMAX * 128];    // GEMM1 output (pre-LN), fp16 packed
__device__ float2   g_lnstat[NMAX];      // per-row (sum, sumsq) of y1, built by k_mma1
__device__ int   g_cnt[NMAX];
__device__ int   g_rs [NMAX + 1];
__device__ int   g_cur[NMAX];
__device__ int2  g_edges[EMAX];
// fragment-ordered fp16 weight images, 64KB each
__device__ uint2 g_w1h[8192];
__device__ uint2 g_w2h[8192];

// ---------------- helpers ----------------
__device__ __forceinline__ uint32_t pack2h(float a, float b) {
    __half2 h = __floats2half2_rn(a, b);
    return *reinterpret_cast<uint32_t*>(&h);
}
__device__ __forceinline__ float2 unpack2h(uint32_t v) {
    __half2 h = *reinterpret_cast<__half2*>(&v);
    return __half22float2(h);
}

// f16 inputs, f32 accum
__device__ __forceinline__ void mma_f32acc(float* d, const uint32_t* a, uint32_t b0, uint32_t b1) {
    asm volatile(
        "mma.sync.aligned.m16n8k16.row.col.f32.f16.f16.f32 "
        "{%0,%1,%2,%3}, {%4,%5,%6,%7}, {%8,%9}, {%0,%1,%2,%3};"
        : "+f"(d[0]), "+f"(d[1]), "+f"(d[2]), "+f"(d[3])
        : "r"(a[0]), "r"(a[1]), "r"(a[2]), "r"(a[3]), "r"(b0), "r"(b1));
}

// ---------------- K0: hn = relu(BN(h)) + degree histogram + zero LN stats ----------------
__global__ void k_hn_hist(const float4* __restrict__ h,
                          const float4* __restrict__ bw, const float4* __restrict__ bb,
                          const float4* __restrict__ bm, const float4* __restrict__ bv,
                          const int* __restrict__ dst, int n, int e)
{
    int i = blockIdx.x * blockDim.x + threadIdx.x;
    if (i < e) atomicAdd(&g_cnt[dst[i]], 1);
    if (i < n) g_lnstat[i] = make_float2(0.f, 0.f);
    if (i >= n * HV) return;
    int j = i & (HV - 1);
    float4 x = h[i];
    float4 w = bw[j], b = bb[j], m = bm[j], v = bv[j];
    float4 o;
    o.x = fmaxf((x.x - m.x) * rsqrtf(v.x + 1e-5f) * w.x + b.x, 0.f);
    o.y = fmaxf((x.y - m.y) * rsqrtf(v.y + 1e-5f) * w.y + b.y, 0.f);
    o.z = fmaxf((x.z - m.z) * rsqrtf(v.z + 1e-5f) * w.z + b.z, 0.f);
    o.w = fmaxf((x.w - m.w) * rsqrtf(v.w + 1e-5f) * w.w + b.w, 0.f);
    ((float4*)g_hn)[i] = o;
}

// ---------------- K1: pipelined exclusive scan (single block) ----------------
__global__ void k_scan(int n)
{
    __shared__ int wsum[32];
    __shared__ int s_carry;
    int tid = threadIdx.x, lane = tid & 31, wid = tid >> 5;
    if (tid == 0) s_carry = 0;
    int nIter = (n + 1023) >> 10;
    int idx = tid;
    int v = (idx < n) ? g_cnt[idx] : 0;      // prime the pipeline
    __syncthreads();
    for (int it = 0; it < nIter; ++it) {
        int nidx = idx + 1024;
        int vnext = (it + 1 < nIter && nidx < n) ? g_cnt[nidx] : 0;  // prefetch
        int x = v;
        #pragma unroll
        for (int o = 1; o < 32; o <<= 1) {
            int u = __shfl_up_sync(0xffffffffu, x, o);
            if (lane >= o) x += u;
        }
        if (lane == 31) wsum[wid] = x;
        __syncthreads();
        if (wid == 0) {
            int w = wsum[lane];
            #pragma unroll
            for (int o = 1; o < 32; o <<= 1) {
                int u = __shfl_up_sync(0xffffffffu, w, o);
                if (lane >= o) w += u;
            }
            wsum[lane] = w;
        }
        __syncthreads();
        int carry = s_carry;
        int excl = x - v + (wid > 0 ? wsum[wid - 1] : 0) + carry;
        if (idx < n) { g_rs[idx] = excl; g_cur[idx] = excl; g_cnt[idx] = 0; }
        __syncthreads();
        if (tid == 0) s_carry = carry + wsum[31];
        __syncthreads();
        idx = nidx; v = vnext;
    }
    if (tid == 0) g_rs[n] = s_carry;
}

// ---------------- K2: scatter edges by dst ----------------
__global__ void k_scatter(const int* __restrict__ src, const int* __restrict__ dst, int e)
{
    int i = blockIdx.x * blockDim.x + threadIdx.x;
    if (i >= e) return;
    int d = dst[i];
    int s = src[i];
    int p = atomicAdd(&g_cur[d], 1);
    g_edges[p] = make_int2(s, i);
}

// ---------------- K3: one-pass softmax aggregation (warp per dst node) ----------------
// ea + edge records via __ldcs (read-once streaming; keeps hn hot in L2)
#define EDGE_ACC(a, hv)                                               \
    {                                                                 \
        float m0 = fmaxf(a.x + hv.x, 0.f) + 1e-7f;                    \
        float m1 = fmaxf(a.y + hv.y, 0.f) + 1e-7f;                    \
        float m2 = fmaxf(a.z + hv.z, 0.f) + 1e-7f;                    \
        float m3 = fmaxf(a.w + hv.w, 0.f) + 1e-7f;                    \
        float e0 = __expf(m0 * t);                                    \
        float e1 = __expf(m1 * t);                                    \
        float e2 = __expf(m2 * t);                                    \
        float e3 = __expf(m3 * t);                                    \
        S.x += e0; P.x = fmaf(m0, e0, P.x);                           \
        S.y += e1; P.y = fmaf(m1, e1, P.y);                           \
        S.z += e2; P.z = fmaf(m2, e2, P.z);                           \
        S.w += e3; P.w = fmaf(m3, e3, P.w);                           \
    }

__global__ void __launch_bounds__(512) k_agg(const float4* __restrict__ ea,
                                             const float* __restrict__ tp, int n)
{
    int warp = (blockIdx.x * blockDim.x + threadIdx.x) >> 5;
    int lane = threadIdx.x & 31;
    if (warp >= n) return;
    float t = __ldg(tp);
    int s0 = g_rs[warp], s1 = g_rs[warp + 1];
    const float4* hn4 = (const float4*)g_hn;
    float4 S = make_float4(0.f, 0.f, 0.f, 0.f);
    float4 P = make_float4(0.f, 0.f, 0.f, 0.f);

    int i = s0;
    for (; i + 4 <= s1; i += 4) {
        int2 q0 = __ldcs(&g_edges[i + 0]);
        int2 q1 = __ldcs(&g_edges[i + 1]);
        int2 q2 = __ldcs(&g_edges[i + 2]);
        int2 q3 = __ldcs(&g_edges[i + 3]);
        float4 a0 = __ldcs(&ea[(size_t)q0.y * HV + lane]);
        float4 h0 = __ldg (&hn4[(size_t)q0.x * HV + lane]);
        float4 a1 = __ldcs(&ea[(size_t)q1.y * HV + lane]);
        float4 h1 = __ldg (&hn4[(size_t)q1.x * HV + lane]);
        float4 a2 = __ldcs(&ea[(size_t)q2.y * HV + lane]);
        float4 h2 = __ldg (&hn4[(size_t)q2.x * HV + lane]);
        float4 a3 = __ldcs(&ea[(size_t)q3.y * HV + lane]);
        float4 h3 = __ldg (&hn4[(size_t)q3.x * HV + lane]);
        EDGE_ACC(a0, h0);
        EDGE_ACC(a1, h1);
        EDGE_ACC(a2, h2);
        EDGE_ACC(a3, h3);
    }
    for (; i < s1; ++i) {
        int2 q = __ldcs(&g_edges[i]);
        float4 a  = __ldcs(&ea[(size_t)q.y * HV + lane]);
        float4 hv = __ldg (&hn4[(size_t)q.x * HV + lane]);
        EDGE_ACC(a, hv);
    }

    float4 hd = hn4[warp * HV + lane];
    float ux = P.x / (S.x + 1e-16f) + hd.x;
    float uy = P.y / (S.y + 1e-16f) + hd.y;
    float uz = P.z / (S.z + 1e-16f) + hd.z;
    float uw = P.w / (S.w + 1e-16f) + hd.w;
    ((uint2*)g_u)[warp * 32 + lane] = make_uint2(pack2h(ux, uy), pack2h(uz, uw));
}

// ---------------- K4: prep fragment-ordered fp16 weight images ----------------
// W1: idx = ks(8)*1024 + nb(32)*32 + lane.  W2: idx = ks(16)*512 + nb(16)*32 + lane.
__global__ void k_prepw(const float* __restrict__ W1, const float* __restrict__ W2)
{
    int idx = blockIdx.x * blockDim.x + threadIdx.x;
    if (idx >= 16384) return;
    const float* W;
    uint2* ih;
    int ks, nb, l, ldn;
    if (idx < 8192) {
        int j = idx;
        ks = j >> 10; nb = (j >> 5) & 31; l = j & 31;
        W = W1; ih = g_w1h; ldn = 256;
    } else {
        int j = idx - 8192;
        ks = j >> 9; nb = (j >> 5) & 15; l = j & 31;
        W = W2; ih = g_w2h; ldn = 128;
    }
    int k0 = ks * 16 + (l & 3) * 2;
    int nn = nb * 8 + (l >> 2);
    float x00 = W[(size_t)(k0 + 0) * ldn + nn];
    float x01 = W[(size_t)(k0 + 1) * ldn + nn];
    float x10 = W[(size_t)(k0 + 8) * ldn + nn];
    float x11 = W[(size_t)(k0 + 9) * ldn + nn];
    ih[idx & 8191] = make_uint2(pack2h(x00, x01), pack2h(x10, x11));
}

// ---------------- K5: GEMM1 via mma.sync  y1 = u @ W1 + b1  (+ LN stat atomics) ----------------
// 304 CTAs = 2/SM; CTA owns a 128-col half (32KB weights); u read as ready fp16 fragments.
#define SMEM_MMA1 (32768 + 512)
__global__ void __launch_bounds__(256, 2) k_mma1(const float* __restrict__ b1,
                                                 int n, int nstrips)
{
    extern __shared__ char smem[];
    uint2* sWh  = (uint2*)smem;             // 4096 (32KB): 8 ks x 16 nb x 32 lanes
    float* s_b1 = (float*)(smem + 32768);   // 128
    int tid = threadIdx.x, wid = tid >> 5, lane = tid & 31;
    int half = blockIdx.x & 1, slot = blockIdx.x >> 1;

    for (int i = tid; i < 4096; i += 256) {
        int ks = i >> 9, rem = i & 511;
        sWh[i] = g_w1h[ks * 1024 + half * 512 + rem];
    }
    if (tid < 128) s_b1[tid] = b1[half * 128 + tid];
    __syncthreads();

    int g = lane >> 2, t = lane & 3;
    int nwarps = 152 * 8;
    for (int strip = slot * 8 + wid; strip < nstrips; strip += nwarps) {
        int rg0 = strip * 16 + g;
        int rg1 = rg0 + 8;
        const uint32_t* u0 = g_u + (size_t)rg0 * 64;   // fp16 row: 64 uint32
        const uint32_t* u1 = g_u + (size_t)rg1 * 64;
        float acc[16][4];
        #pragma unroll
        for (int nb = 0; nb < 16; ++nb) {
            float bx = s_b1[nb * 8 + t * 2];
            float by = s_b1[nb * 8 + t * 2 + 1];
            acc[nb][0] = bx; acc[nb][1] = by;
            acc[nb][2] = bx; acc[nb][3] = by;
        }
        #pragma unroll
        for (int ks = 0; ks < 8; ++ks) {
            uint32_t ah[4];
            ah[0] = u0[ks * 8 + t];
            ah[1] = u1[ks * 8 + t];
            ah[2] = u0[ks * 8 + t + 4];
            ah[3] = u1[ks * 8 + t + 4];
            const uint2* wh = sWh + ks * 512 + lane;
            #pragma unroll
            for (int nb = 0; nb < 16; ++nb) {
                uint2 bh = wh[nb * 32];
                mma_f32acc(acc[nb], ah, bh.x, bh.y);
            }
        }

        // ---- LN partial stats over this half's 128 cols; quad-reduce; 2 atomics/row ----
        float sA = 0.f, s2A = 0.f, sB = 0.f, s2B = 0.f;
        #pragma unroll
        for (int nb = 0; nb < 16; ++nb) {
            sA += acc[nb][0] + acc[nb][1];
            s2A = fmaf(acc[nb][0], acc[nb][0], fmaf(acc[nb][1], acc[nb][1], s2A));
            sB += acc[nb][2] + acc[nb][3];
            s2B = fmaf(acc[nb][2], acc[nb][2], fmaf(acc[nb][3], acc[nb][3], s2B));
        }
        #pragma unroll
        for (int o = 1; o < 4; o <<= 1) {
            sA  += __shfl_xor_sync(0xffffffffu, sA, o);
            s2A += __shfl_xor_sync(0xffffffffu, s2A, o);
            sB  += __shfl_xor_sync(0xffffffffu, sB, o);
            s2B += __shfl_xor_sync(0xffffffffu, s2B, o);
        }
        if (t == 0) {
            if (rg0 < n) {
                atomicAdd(&g_lnstat[rg0].x, sA);
                atomicAdd(&g_lnstat[rg0].y, s2A);
            }
            if (rg1 < n) {
                atomicAdd(&g_lnstat[rg1].x, sB);
                atomicAdd(&g_lnstat[rg1].y, s2B);
            }
        }

        // ---- store y1 as fp16 (one uint32 per nb per row) ----
        #pragma unroll
        for (int nb = 0; nb < 16; ++nb) {
            int ci = half * 64 + nb * 4 + t;      // uint32 index within row of 128
            if (rg0 < n) g_y1[(size_t)rg0 * 128 + ci] = pack2h(acc[nb][0], acc[nb][1]);
            if (rg1 < n) g_y1[(size_t)rg1 * 128 + ci] = pack2h(acc[nb][2], acc[nb][3]);
        }
    }
}

// ---------------- K6: GEMM2 via mma.sync  out = relu(LN(y1)) @ W2 + b2 + h ----------------
// 304 CTAs = 2/SM; CTA owns a 64-col half; LN mean/scale from g_lnstat; y1 read as fp16.
#define SMEM_MMA2 (32768 + 2304)
__global__ void __launch_bounds__(256, 2) k_mma2(const float* __restrict__ b2,
                                                 const float* __restrict__ lnw,
                                                 const float* __restrict__ lnb,
                                                 const float* __restrict__ hres,
                                                 float* __restrict__ out,
                                                 int n, int nstrips)
{
    extern __shared__ char smem[];
    uint2* sWh   = (uint2*)smem;                     // 4096 (32KB): 16 ks x 8 nb x 32 lanes
    float* s_lnw = (float*)(smem + 32768);           // 256
    float* s_lnb = (float*)(smem + 32768 + 1024);    // 256
    float* s_b2  = (float*)(smem + 32768 + 2048);    // 64
    int tid = threadIdx.x, wid = tid >> 5, lane = tid & 31;
    int half = blockIdx.x & 1, slot = blockIdx.x >> 1;

    for (int i = tid; i < 4096; i += 256) {
        int ks = i >> 8, rem = i & 255;
        sWh[i] = g_w2h[ks * 512 + half * 256 + rem];
    }
    if (tid < 256) { s_lnw[tid] = lnw[tid]; s_lnb[tid] = lnb[tid]; }
    if (tid < 64) s_b2[tid] = b2[half * 64 + tid];
    __syncthreads();

    int g = lane >> 2, t = lane & 3;
    int nwarps = 152 * 8;
    for (int strip = slot * 8 + wid; strip < nstrips; strip += nwarps) {
        int rg0 = strip * 16 + g, rg1 = rg0 + 8;

        float2 stA = (rg0 < n) ? g_lnstat[rg0] : make_float2(0.f, 0.f);
        float2 stB = (rg1 < n) ? g_lnstat[rg1] : make_float2(0.f, 0.f);
        float meanA = stA.x * (1.f / 256.f);
        float varA  = fmaxf(stA.y * (1.f / 256.f) - meanA * meanA, 0.f);
        float scaleA = rsqrtf(varA + 1e-5f);
        float meanB = stB.x * (1.f / 256.f);
        float varB  = fmaxf(stB.y * (1.f / 256.f) - meanB * meanB, 0.f);
        float scaleB = rsqrtf(varB + 1e-5f);

        const uint32_t* y0 = g_y1 + (size_t)rg0 * 128;
        const uint32_t* y1 = g_y1 + (size_t)rg1 * 128;
        float acc[8][4];
        #pragma unroll
        for (int nb = 0; nb < 8; ++nb) {
            acc[nb][0] = 0.f; acc[nb][1] = 0.f; acc[nb][2] = 0.f; acc[nb][3] = 0.f;
        }
        #pragma unroll
        for (int ks = 0; ks < 16; ++ks) {
            int k0 = ks * 16 + t * 2;
            float2 v00 = unpack2h(y0[ks * 8 + t]);
            float2 v01 = unpack2h(y0[ks * 8 + t + 4]);
            float2 v10 = unpack2h(y1[ks * 8 + t]);
            float2 v11 = unpack2h(y1[ks * 8 + t + 4]);
            float2 w0 = *(const float2*)(s_lnw + k0);
            float2 w1 = *(const float2*)(s_lnw + k0 + 8);
            float2 z0 = *(const float2*)(s_lnb + k0);
            float2 z1 = *(const float2*)(s_lnb + k0 + 8);
            float x00 = fmaxf((v00.x - meanA) * scaleA * w0.x + z0.x, 0.f);
            float x01 = fmaxf((v00.y - meanA) * scaleA * w0.y + z0.y, 0.f);
            float x02 = fmaxf((v01.x - meanA) * scaleA * w1.x + z1.x, 0.f);
            float x03 = fmaxf((v01.y - meanA) * scaleA * w1.y + z1.y, 0.f);
            float x10 = fmaxf((v10.x - meanB) * scaleB * w0.x + z0.x, 0.f);
            float x11 = fmaxf((v10.y - meanB) * scaleB * w0.y + z0.y, 0.f);
            float x12 = fmaxf((v11.x - meanB) * scaleB * w1.x + z1.x, 0.f);
            float x13 = fmaxf((v11.y - meanB) * scaleB * w1.y + z1.y, 0.f);
            uint32_t ah[4];
            ah[0] = pack2h(x00, x01);
            ah[1] = pack2h(x10, x11);
            ah[2] = pack2h(x02, x03);
            ah[3] = pack2h(x12, x13);
            const uint2* wh = sWh + ks * 256 + lane;
            #pragma unroll
            for (int nb = 0; nb < 8; ++nb) {
                uint2 bh = wh[nb * 32];
                mma_f32acc(acc[nb], ah, bh.x, bh.y);
            }
        }
        #pragma unroll
        for (int nb = 0; nb < 8; ++nb) {
            int col = half * 64 + nb * 8 + t * 2;
            float2 bb = *(const float2*)(s_b2 + nb * 8 + t * 2);
            if (rg0 < n) {
                float2 hv = *(const float2*)(hres + (size_t)rg0 * 128 + col);
                *(float2*)(out + (size_t)rg0 * 128 + col) =
                    make_float2(acc[nb][0] + bb.x + hv.x, acc[nb][1] + bb.y + hv.y);
            }
            if (rg1 < n) {
                float2 hv = *(const float2*)(hres + (size_t)rg1 * 128 + col);
                *(float2*)(out + (size_t)rg1 * 128 + col) =
                    make_float2(acc[nb][2] + bb.x + hv.x, acc[nb][3] + bb.y + hv.y);
            }
        }
    }
}

// ---------------- launch ----------------
extern "C" void kernel_launch(void* const* d_in, const int* in_sizes, int n_in,
                              void* d_out, int out_size)
{
    const float* h   = (const float*)d_in[0];
    const int*   ei  = (const int*)  d_in[1];
    const float* ea  = (const float*)d_in[2];
    const float* bw  = (const float*)d_in[3];
    const float* bb  = (const float*)d_in[4];
    const float* bm  = (const float*)d_in[5];
    const float* bv  = (const float*)d_in[6];
    const float* tp  = (const float*)d_in[7];
    const float* W1  = (const float*)d_in[8];
    const float* b1  = (const float*)d_in[9];
    const float* lnw = (const float*)d_in[10];
    const float* lnb = (const float*)d_in[11];
    const float* W2  = (const float*)d_in[12];
    const float* b2  = (const float*)d_in[13];

    int n = in_sizes[0] / HF;
    int e = in_sizes[2] / HF;
    const int* src = ei;
    const int* dst = ei + e;
    int nstrips = (n + 15) / 16;

    cudaFuncSetAttribute(k_mma1, cudaFuncAttributeMaxDynamicSharedMemorySize, SMEM_MMA1);
    cudaFuncSetAttribute(k_mma2, cudaFuncAttributeMaxDynamicSharedMemorySize, SMEM_MMA2);

    k_hn_hist<<<(n * HV + 255) / 256, 256>>>((const float4*)h, (const float4*)bw,
                                             (const float4*)bb, (const float4*)bm,
                                             (const float4*)bv, dst, n, e);
    k_scan<<<1, 1024>>>(n);
    k_scatter<<<(e + 255) / 256, 256>>>(src, dst, e);
    k_agg<<<(n + 15) / 16, 512>>>((const float4*)ea, tp, n);    // <- ncu capture lands here
    k_prepw<<<64, 256>>>(W1, W2);
    k_mma1<<<304, 256, SMEM_MMA1>>>(b1, n, nstrips);
    k_mma2<<<304, 256, SMEM_MMA2>>>(b2, lnw, lnb, h, (float*)d_out, n, nstrips);
}

// round 16
// speedup vs baseline: 1.3160x; 1.0090x over previous
#include <cuda_runtime.h>
#include <cuda_fp16.h>
#include <cstdint>

#define HF 128
#define HV 32           // float4 per feature row
#define NMAX 50048
#define EMAX 800032

// ---------------- scratch (static device memory; no allocation) ----------------
__device__ uint32_t g_hn[NMAX * 64];     // relu(BN(x)), fp16 packed (half2 x 64 per row)
__device__ uint32_t g_u [NMAX * 64];     // agg + hn, fp16 (half2-packed), MLP input
__device__ uint32_t g_y1[NMAX * 128];    // GEMM1 output (pre-LN), fp16 packed
__device__ float2   g_lnstat[NMAX];      // per-row (sum, sumsq) of y1, built by k_mma1
__device__ int   g_cnt[NMAX];
__device__ int   g_rs [NMAX + 1];
__device__ int   g_cur[NMAX];
__device__ int2  g_edges[EMAX];
// fragment-ordered fp16 weight images, 64KB each
__device__ uint2 g_w1h[8192];
__device__ uint2 g_w2h[8192];

// ---------------- helpers ----------------
__device__ __forceinline__ uint32_t pack2h(float a, float b) {
    __half2 h = __floats2half2_rn(a, b);
    return *reinterpret_cast<uint32_t*>(&h);
}
__device__ __forceinline__ float2 unpack2h(uint32_t v) {
    __half2 h = *reinterpret_cast<__half2*>(&v);
    return __half22float2(h);
}
__device__ __forceinline__ float4 unpack4h(uint2 v) {
    float2 a = unpack2h(v.x);
    float2 b = unpack2h(v.y);
    return make_float4(a.x, a.y, b.x, b.y);
}

// f16 inputs, f32 accum
__device__ __forceinline__ void mma_f32acc(float* d, const uint32_t* a, uint32_t b0, uint32_t b1) {
    asm volatile(
        "mma.sync.aligned.m16n8k16.row.col.f32.f16.f16.f32 "
        "{%0,%1,%2,%3}, {%4,%5,%6,%7}, {%8,%9}, {%0,%1,%2,%3};"
        : "+f"(d[0]), "+f"(d[1]), "+f"(d[2]), "+f"(d[3])
        : "r"(a[0]), "r"(a[1]), "r"(a[2]), "r"(a[3]), "r"(b0), "r"(b1));
}

// ---------------- K0: hn = relu(BN(h)) (fp16) + degree histogram + zero LN stats ----------------
__global__ void k_hn_hist(const float4* __restrict__ h,
                          const float4* __restrict__ bw, const float4* __restrict__ bb,
                          const float4* __restrict__ bm, const float4* __restrict__ bv,
                          const int* __restrict__ dst, int n, int e)
{
    int i = blockIdx.x * blockDim.x + threadIdx.x;
    if (i < e) atomicAdd(&g_cnt[dst[i]], 1);
    if (i < n) g_lnstat[i] = make_float2(0.f, 0.f);
    if (i >= n * HV) return;
    int j = i & (HV - 1);
    float4 x = h[i];
    float4 w = bw[j], b = bb[j], m = bm[j], v = bv[j];
    float ox = fmaxf((x.x - m.x) * rsqrtf(v.x + 1e-5f) * w.x + b.x, 0.f);
    float oy = fmaxf((x.y - m.y) * rsqrtf(v.y + 1e-5f) * w.y + b.y, 0.f);
    float oz = fmaxf((x.z - m.z) * rsqrtf(v.z + 1e-5f) * w.z + b.z, 0.f);
    float ow = fmaxf((x.w - m.w) * rsqrtf(v.w + 1e-5f) * w.w + b.w, 0.f);
    ((uint2*)g_hn)[i] = make_uint2(pack2h(ox, oy), pack2h(oz, ow));
}

// ---------------- K1: pipelined exclusive scan (single block) ----------------
__global__ void k_scan(int n)
{
    __shared__ int wsum[32];
    __shared__ int s_carry;
    int tid = threadIdx.x, lane = tid & 31, wid = tid >> 5;
    if (tid == 0) s_carry = 0;
    int nIter = (n + 1023) >> 10;
    int idx = tid;
    int v = (idx < n) ? g_cnt[idx] : 0;      // prime the pipeline
    __syncthreads();
    for (int it = 0; it < nIter; ++it) {
        int nidx = idx + 1024;
        int vnext = (it + 1 < nIter && nidx < n) ? g_cnt[nidx] : 0;  // prefetch
        int x = v;
        #pragma unroll
        for (int o = 1; o < 32; o <<= 1) {
            int u = __shfl_up_sync(0xffffffffu, x, o);
            if (lane >= o) x += u;
        }
        if (lane == 31) wsum[wid] = x;
        __syncthreads();
        if (wid == 0) {
            int w = wsum[lane];
            #pragma unroll
            for (int o = 1; o < 32; o <<= 1) {
                int u = __shfl_up_sync(0xffffffffu, w, o);
                if (lane >= o) w += u;
            }
            wsum[lane] = w;
        }
        __syncthreads();
        int carry = s_carry;
        int excl = x - v + (wid > 0 ? wsum[wid - 1] : 0) + carry;
        if (idx < n) { g_rs[idx] = excl; g_cur[idx] = excl; g_cnt[idx] = 0; }
        __syncthreads();
        if (tid == 0) s_carry = carry + wsum[31];
        __syncthreads();
        idx = nidx; v = vnext;
    }
    if (tid == 0) g_rs[n] = s_carry;
}

// ---------------- K2: scatter edges by dst ----------------
__global__ void k_scatter(const int* __restrict__ src, const int* __restrict__ dst, int e)
{
    int i = blockIdx.x * blockDim.x + threadIdx.x;
    if (i >= e) return;
    int d = dst[i];
    int s = src[i];
    int p = atomicAdd(&g_cur[d], 1);
    g_edges[p] = make_int2(s, i);
}

// ---------------- K3: one-pass softmax aggregation (warp per dst node) ----------------
// ea + edge records via __ldcs (read-once streaming); hn fp16 gathers (half L2 traffic)
#define EDGE_ACC(a, hv)                                               \
    {                                                                 \
        float m0 = fmaxf(a.x + hv.x, 0.f) + 1e-7f;                    \
        float m1 = fmaxf(a.y + hv.y, 0.f) + 1e-7f;                    \
        float m2 = fmaxf(a.z + hv.z, 0.f) + 1e-7f;                    \
        float m3 = fmaxf(a.w + hv.w, 0.f) + 1e-7f;                    \
        float e0 = __expf(m0 * t);                                    \
        float e1 = __expf(m1 * t);                                    \
        float e2 = __expf(m2 * t);                                    \
        float e3 = __expf(m3 * t);                                    \
        S.x += e0; P.x = fmaf(m0, e0, P.x);                           \
        S.y += e1; P.y = fmaf(m1, e1, P.y);                           \
        S.z += e2; P.z = fmaf(m2, e2, P.z);                           \
        S.w += e3; P.w = fmaf(m3, e3, P.w);                           \
    }

__global__ void __launch_bounds__(512) k_agg(const float4* __restrict__ ea,
                                             const float* __restrict__ tp, int n)
{
    int warp = (blockIdx.x * blockDim.x + threadIdx.x) >> 5;
    int lane = threadIdx.x & 31;
    if (warp >= n) return;
    float t = __ldg(tp);
    int s0 = g_rs[warp], s1 = g_rs[warp + 1];
    const uint2* hn2 = (const uint2*)g_hn;
    float4 S = make_float4(0.f, 0.f, 0.f, 0.f);
    float4 P = make_float4(0.f, 0.f, 0.f, 0.f);

    int i = s0;
    for (; i + 4 <= s1; i += 4) {
        int2 q0 = __ldcs(&g_edges[i + 0]);
        int2 q1 = __ldcs(&g_edges[i + 1]);
        int2 q2 = __ldcs(&g_edges[i + 2]);
        int2 q3 = __ldcs(&g_edges[i + 3]);
        float4 a0 = __ldcs(&ea[(size_t)q0.y * HV + lane]);
        uint2  g0 = __ldg (&hn2[(size_t)q0.x * 32 + lane]);
        float4 a1 = __ldcs(&ea[(size_t)q1.y * HV + lane]);
        uint2  g1 = __ldg (&hn2[(size_t)q1.x * 32 + lane]);
        float4 a2 = __ldcs(&ea[(size_t)q2.y * HV + lane]);
        uint2  g2 = __ldg (&hn2[(size_t)q2.x * 32 + lane]);
        float4 a3 = __ldcs(&ea[(size_t)q3.y * HV + lane]);
        uint2  g3 = __ldg (&hn2[(size_t)q3.x * 32 + lane]);
        float4 h0 = unpack4h(g0);
        float4 h1 = unpack4h(g1);
        float4 h2 = unpack4h(g2);
        float4 h3 = unpack4h(g3);
        EDGE_ACC(a0, h0);
        EDGE_ACC(a1, h1);
        EDGE_ACC(a2, h2);
        EDGE_ACC(a3, h3);
    }
    for (; i < s1; ++i) {
        int2 q = __ldcs(&g_edges[i]);
        float4 a  = __ldcs(&ea[(size_t)q.y * HV + lane]);
        float4 hv = unpack4h(__ldg(&hn2[(size_t)q.x * 32 + lane]));
        EDGE_ACC(a, hv);
    }

    float4 hd = unpack4h(hn2[(size_t)warp * 32 + lane]);
    float ux = P.x / (S.x + 1e-16f) + hd.x;
    float uy = P.y / (S.y + 1e-16f) + hd.y;
    float uz = P.z / (S.z + 1e-16f) + hd.z;
    float uw = P.w / (S.w + 1e-16f) + hd.w;
    ((uint2*)g_u)[warp * 32 + lane] = make_uint2(pack2h(ux, uy), pack2h(uz, uw));
}

// ---------------- K4: prep fragment-ordered fp16 weight images ----------------
// W1: idx = ks(8)*1024 + nb(32)*32 + lane.  W2: idx = ks(16)*512 + nb(16)*32 + lane.
__global__ void k_prepw(const float* __restrict__ W1, const float* __restrict__ W2)
{
    int idx = blockIdx.x * blockDim.x + threadIdx.x;
    if (idx >= 16384) return;
    const float* W;
    uint2* ih;
    int ks, nb, l, ldn;
    if (idx < 8192) {
        int j = idx;
        ks = j >> 10; nb = (j >> 5) & 31; l = j & 31;
        W = W1; ih = g_w1h; ldn = 256;
    } else {
        int j = idx - 8192;
        ks = j >> 9; nb = (j >> 5) & 15; l = j & 31;
        W = W2; ih = g_w2h; ldn = 128;
    }
    int k0 = ks * 16 + (l & 3) * 2;
    int nn = nb * 8 + (l >> 2);
    float x00 = W[(size_t)(k0 + 0) * ldn + nn];
    float x01 = W[(size_t)(k0 + 1) * ldn + nn];
    float x10 = W[(size_t)(k0 + 8) * ldn + nn];
    float x11 = W[(size_t)(k0 + 9) * ldn + nn];
    ih[idx & 8191] = make_uint2(pack2h(x00, x01), pack2h(x10, x11));
}

// ---------------- K5: GEMM1 via mma.sync  y1 = u @ W1 + b1  (+ LN stat atomics) ----------------
// 304 CTAs = 2/SM; CTA owns a 128-col half (32KB weights); u read as ready fp16 fragments.
#define SMEM_MMA1 (32768 + 512)
__global__ void __launch_bounds__(256, 2) k_mma1(const float* __restrict__ b1,
                                                 int n, int nstrips)
{
    extern __shared__ char smem[];
    uint2* sWh  = (uint2*)smem;             // 4096 (32KB): 8 ks x 16 nb x 32 lanes
    float* s_b1 = (float*)(smem + 32768);   // 128
    int tid = threadIdx.x, wid = tid >> 5, lane = tid & 31;
    int half = blockIdx.x & 1, slot = blockIdx.x >> 1;

    for (int i = tid; i < 4096; i += 256) {
        int ks = i >> 9, rem = i & 511;
        sWh[i] = g_w1h[ks * 1024 + half * 512 + rem];
    }
    if (tid < 128) s_b1[tid] = b1[half * 128 + tid];
    __syncthreads();

    int g = lane >> 2, t = lane & 3;
    int nwarps = 152 * 8;
    for (int strip = slot * 8 + wid; strip < nstrips; strip += nwarps) {
        int rg0 = strip * 16 + g;
        int rg1 = rg0 + 8;
        const uint32_t* u0 = g_u + (size_t)rg0 * 64;   // fp16 row: 64 uint32
        const uint32_t* u1 = g_u + (size_t)rg1 * 64;
        float acc[16][4];
        #pragma unroll
        for (int nb = 0; nb < 16; ++nb) {
            float bx = s_b1[nb * 8 + t * 2];
            float by = s_b1[nb * 8 + t * 2 + 1];
            acc[nb][0] = bx; acc[nb][1] = by;
            acc[nb][2] = bx; acc[nb][3] = by;
        }
        #pragma unroll
        for (int ks = 0; ks < 8; ++ks) {
            uint32_t ah[4];
            ah[0] = u0[ks * 8 + t];
            ah[1] = u1[ks * 8 + t];
            ah[2] = u0[ks * 8 + t + 4];
            ah[3] = u1[ks * 8 + t + 4];
            const uint2* wh = sWh + ks * 512 + lane;
            #pragma unroll
            for (int nb = 0; nb < 16; ++nb) {
                uint2 bh = wh[nb * 32];
                mma_f32acc(acc[nb], ah, bh.x, bh.y);
            }
        }

        // ---- LN partial stats over this half's 128 cols; quad-reduce; 2 atomics/row ----
        float sA = 0.f, s2A = 0.f, sB = 0.f, s2B = 0.f;
        #pragma unroll
        for (int nb = 0; nb < 16; ++nb) {
            sA += acc[nb][0] + acc[nb][1];
            s2A = fmaf(acc[nb][0], acc[nb][0], fmaf(acc[nb][1], acc[nb][1], s2A));
            sB += acc[nb][2] + acc[nb][3];
            s2B = fmaf(acc[nb][2], acc[nb][2], fmaf(acc[nb][3], acc[nb][3], s2B));
        }
        #pragma unroll
        for (int o = 1; o < 4; o <<= 1) {
            sA  += __shfl_xor_sync(0xffffffffu, sA, o);
            s2A += __shfl_xor_sync(0xffffffffu, s2A, o);
            sB  += __shfl_xor_sync(0xffffffffu, sB, o);
            s2B += __shfl_xor_sync(0xffffffffu, s2B, o);
        }
        if (t == 0) {
            if (rg0 < n) {
                atomicAdd(&g_lnstat[rg0].x, sA);
                atomicAdd(&g_lnstat[rg0].y, s2A);
            }
            if (rg1 < n) {
                atomicAdd(&g_lnstat[rg1].x, sB);
                atomicAdd(&g_lnstat[rg1].y, s2B);
            }
        }

        // ---- store y1 as fp16 (one uint32 per nb per row) ----
        #pragma unroll
        for (int nb = 0; nb < 16; ++nb) {
            int ci = half * 64 + nb * 4 + t;      // uint32 index within row of 128
            if (rg0 < n) g_y1[(size_t)rg0 * 128 + ci] = pack2h(acc[nb][0], acc[nb][1]);
            if (rg1 < n) g_y1[(size_t)rg1 * 128 + ci] = pack2h(acc[nb][2], acc[nb][3]);
        }
    }
}

// ---------------- K6: GEMM2 via mma.sync  out = relu(LN(y1)) @ W2 + b2 + h ----------------
// 304 CTAs = 2/SM; CTA owns a 64-col half; LN mean/scale from g_lnstat; y1 read as fp16.
#define SMEM_MMA2 (32768 + 2304)
__global__ void __launch_bounds__(256, 2) k_mma2(const float* __restrict__ b2,
                                                 const float* __restrict__ lnw,
                                                 const float* __restrict__ lnb,
                                                 const float* __restrict__ hres,
                                                 float* __restrict__ out,
                                                 int n, int nstrips)
{
    extern __shared__ char smem[];
    uint2* sWh   = (uint2*)smem;                     // 4096 (32KB): 16 ks x 8 nb x 32 lanes
    float* s_lnw = (float*)(smem + 32768);           // 256
    float* s_lnb = (float*)(smem + 32768 + 1024);    // 256
    float* s_b2  = (float*)(smem + 32768 + 2048);    // 64
    int tid = threadIdx.x, wid = tid >> 5, lane = tid & 31;
    int half = blockIdx.x & 1, slot = blockIdx.x >> 1;

    for (int i = tid; i < 4096; i += 256) {
        int ks = i >> 8, rem = i & 255;
        sWh[i] = g_w2h[ks * 512 + half * 256 + rem];
    }
    if (tid < 256) { s_lnw[tid] = lnw[tid]; s_lnb[tid] = lnb[tid]; }
    if (tid < 64) s_b2[tid] = b2[half * 64 + tid];
    __syncthreads();

    int g = lane >> 2, t = lane & 3;
    int nwarps = 152 * 8;
    for (int strip = slot * 8 + wid; strip < nstrips; strip += nwarps) {
        int rg0 = strip * 16 + g, rg1 = rg0 + 8;

        float2 stA = (rg0 < n) ? g_lnstat[rg0] : make_float2(0.f, 0.f);
        float2 stB = (rg1 < n) ? g_lnstat[rg1] : make_float2(0.f, 0.f);
        float meanA = stA.x * (1.f / 256.f);
        float varA  = fmaxf(stA.y * (1.f / 256.f) - meanA * meanA, 0.f);
        float scaleA = rsqrtf(varA + 1e-5f);
        float meanB = stB.x * (1.f / 256.f);
        float varB  = fmaxf(stB.y * (1.f / 256.f) - meanB * meanB, 0.f);
        float scaleB = rsqrtf(varB + 1e-5f);

        const uint32_t* y0 = g_y1 + (size_t)rg0 * 128;
        const uint32_t* y1 = g_y1 + (size_t)rg1 * 128;
        float acc[8][4];
        #pragma unroll
        for (int nb = 0; nb < 8; ++nb) {
            acc[nb][0] = 0.f; acc[nb][1] = 0.f; acc[nb][2] = 0.f; acc[nb][3] = 0.f;
        }
        #pragma unroll
        for (int ks = 0; ks < 16; ++ks) {
            int k0 = ks * 16 + t * 2;
            float2 v00 = unpack2h(y0[ks * 8 + t]);
            float2 v01 = unpack2h(y0[ks * 8 + t + 4]);
            float2 v10 = unpack2h(y1[ks * 8 + t]);
            float2 v11 = unpack2h(y1[ks * 8 + t + 4]);
            float2 w0 = *(const float2*)(s_lnw + k0);
            float2 w1 = *(const float2*)(s_lnw + k0 + 8);
            float2 z0 = *(const float2*)(s_lnb + k0);
            float2 z1 = *(const float2*)(s_lnb + k0 + 8);
            float x00 = fmaxf((v00.x - meanA) * scaleA * w0.x + z0.x, 0.f);
            float x01 = fmaxf((v00.y - meanA) * scaleA * w0.y + z0.y, 0.f);
            float x02 = fmaxf((v01.x - meanA) * scaleA * w1.x + z1.x, 0.f);
            float x03 = fmaxf((v01.y - meanA) * scaleA * w1.y + z1.y, 0.f);
            float x10 = fmaxf((v10.x - meanB) * scaleB * w0.x + z0.x, 0.f);
            float x11 = fmaxf((v10.y - meanB) * scaleB * w0.y + z0.y, 0.f);
            float x12 = fmaxf((v11.x - meanB) * scaleB * w1.x + z1.x, 0.f);
            float x13 = fmaxf((v11.y - meanB) * scaleB * w1.y + z1.y, 0.f);
            uint32_t ah[4];
            ah[0] = pack2h(x00, x01);
            ah[1] = pack2h(x10, x11);
            ah[2] = pack2h(x02, x03);
            ah[3] = pack2h(x12, x13);
            const uint2* wh = sWh + ks * 256 + lane;
            #pragma unroll
            for (int nb = 0; nb < 8; ++nb) {
                uint2 bh = wh[nb * 32];
                mma_f32acc(acc[nb], ah, bh.x, bh.y);
            }
        }
        #pragma unroll
        for (int nb = 0; nb < 8; ++nb) {
            int col = half * 64 + nb * 8 + t * 2;
            float2 bb = *(const float2*)(s_b2 + nb * 8 + t * 2);
            if (rg0 < n) {
                float2 hv = *(const float2*)(hres + (size_t)rg0 * 128 + col);
                *(float2*)(out + (size_t)rg0 * 128 + col) =
                    make_float2(acc[nb][0] + bb.x + hv.x, acc[nb][1] + bb.y + hv.y);
            }
            if (rg1 < n) {
                float2 hv = *(const float2*)(hres + (size_t)rg1 * 128 + col);
                *(float2*)(out + (size_t)rg1 * 128 + col) =
                    make_float2(acc[nb][2] + bb.x + hv.x, acc[nb][3] + bb.y + hv.y);
            }
        }
    }
}

// ---------------- launch ----------------
extern "C" void kernel_launch(void* const* d_in, const int* in_sizes, int n_in,
                              void* d_out, int out_size)
{
    const float* h   = (const float*)d_in[0];
    const int*   ei  = (const int*)  d_in[1];
    const float* ea  = (const float*)d_in[2];
    const float* bw  = (const float*)d_in[3];
    const float* bb  = (const float*)d_in[4];
    const float* bm  = (const float*)d_in[5];
    const float* bv  = (const float*)d_in[6];
    const float* tp  = (const float*)d_in[7];
    const float* W1  = (const float*)d_in[8];
    const float* b1  = (const float*)d_in[9];
    const float* lnw = (const float*)d_in[10];
    const float* lnb = (const float*)d_in[11];
    const float* W2  = (const float*)d_in[12];
    const float* b2  = (const float*)d_in[13];

    int n = in_sizes[0] / HF;
    int e = in_sizes[2] / HF;
    const int* src = ei;
    const int* dst = ei + e;
    int nstrips = (n + 15) / 16;

    cudaFuncSetAttribute(k_mma1, cudaFuncAttributeMaxDynamicSharedMemorySize, SMEM_MMA1);
    cudaFuncSetAttribute(k_mma2, cudaFuncAttributeMaxDynamicSharedMemorySize, SMEM_MMA2);

    k_hn_hist<<<(n * HV + 255) / 256, 256>>>((const float4*)h, (const float4*)bw,
                                             (const float4*)bb, (const float4*)bm,
                                             (const float4*)bv, dst, n, e);
    k_scan<<<1, 1024>>>(n);
    k_scatter<<<(e + 255) / 256, 256>>>(src, dst, e);
    k_agg<<<(n + 15) / 16, 512>>>((const float4*)ea, tp, n);    // <- ncu capture lands here
    k_prepw<<<64, 256>>>(W1, W2);
    k_mma1<<<304, 256, SMEM_MMA1>>>(b1, n, nstrips);
    k_mma2<<<304, 256, SMEM_MMA2>>>(b2, lnw, lnb, h, (float*)d_out, n, nstrips);
}

// round 17
// speedup vs baseline: 1.3279x; 1.0090x over previous
#include <cuda_runtime.h>
#include <cuda_fp16.h>
#include <cstdint>

#define HF 128
#define HV 32           // float4 per feature row
#define NMAX 50048
#define EMAX 800032

// ---------------- scratch (static device memory; no allocation) ----------------
__device__ uint32_t g_hn[NMAX * 64];     // relu(BN(x)), fp16 packed (half2 x 64 per row)
__device__ uint32_t g_u [NMAX * 64];     // agg + hn, fp16 (half2-packed), MLP input
__device__ uint32_t g_y1[NMAX * 128];    // GEMM1 output (pre-LN), fp16 packed
__device__ float2   g_lnstat[NMAX];      // per-row (sum, sumsq) of y1, built by k_mma1
__device__ int   g_cnt[NMAX];
__device__ int   g_rs [NMAX + 1];
__device__ int   g_cur[NMAX];
__device__ int2  g_edges[EMAX];
// fragment-ordered fp16 weight images, 64KB each
__device__ uint2 g_w1h[8192];
__device__ uint2 g_w2h[8192];

// ---------------- helpers ----------------
__device__ __forceinline__ uint32_t pack2h(float a, float b) {
    __half2 h = __floats2half2_rn(a, b);
    return *reinterpret_cast<uint32_t*>(&h);
}
__device__ __forceinline__ float2 unpack2h(uint32_t v) {
    __half2 h = *reinterpret_cast<__half2*>(&v);
    return __half22float2(h);
}
__device__ __forceinline__ float4 unpack4h(uint2 v) {
    float2 a = unpack2h(v.x);
    float2 b = unpack2h(v.y);
    return make_float4(a.x, a.y, b.x, b.y);
}

// f16 inputs, f32 accum
__device__ __forceinline__ void mma_f32acc(float* d, const uint32_t* a, uint32_t b0, uint32_t b1) {
    asm volatile(
        "mma.sync.aligned.m16n8k16.row.col.f32.f16.f16.f32 "
        "{%0,%1,%2,%3}, {%4,%5,%6,%7}, {%8,%9}, {%0,%1,%2,%3};"
        : "+f"(d[0]), "+f"(d[1]), "+f"(d[2]), "+f"(d[3])
        : "r"(a[0]), "r"(a[1]), "r"(a[2]), "r"(a[3]), "r"(b0), "r"(b1));
}

// ---------------- K0: hn = relu(BN(h)) (fp16) + degree histogram + zero LN stats ----------------
__global__ void k_hn_hist(const float4* __restrict__ h,
                          const float4* __restrict__ bw, const float4* __restrict__ bb,
                          const float4* __restrict__ bm, const float4* __restrict__ bv,
                          const int* __restrict__ dst, int n, int e)
{
    int i = blockIdx.x * blockDim.x + threadIdx.x;
    if (i < e) atomicAdd(&g_cnt[dst[i]], 1);
    if (i < n) g_lnstat[i] = make_float2(0.f, 0.f);
    if (i >= n * HV) return;
    int j = i & (HV - 1);
    float4 x = h[i];
    float4 w = bw[j], b = bb[j], m = bm[j], v = bv[j];
    float ox = fmaxf((x.x - m.x) * rsqrtf(v.x + 1e-5f) * w.x + b.x, 0.f);
    float oy = fmaxf((x.y - m.y) * rsqrtf(v.y + 1e-5f) * w.y + b.y, 0.f);
    float oz = fmaxf((x.z - m.z) * rsqrtf(v.z + 1e-5f) * w.z + b.z, 0.f);
    float ow = fmaxf((x.w - m.w) * rsqrtf(v.w + 1e-5f) * w.w + b.w, 0.f);
    ((uint2*)g_hn)[i] = make_uint2(pack2h(ox, oy), pack2h(oz, ow));
}

// ---------------- K1: block 0 = pipelined exclusive scan; blocks 1..16 = weight prep ----------------
__global__ void __launch_bounds__(1024) k_scan_prepw(int n,
                                                     const float* __restrict__ W1,
                                                     const float* __restrict__ W2)
{
    int tid = threadIdx.x;
    if (blockIdx.x > 0) {
        // ---- weight prep: fragment-ordered fp16 images ----
        int idx = (blockIdx.x - 1) * 1024 + tid;     // [0, 16384)
        const float* W;
        uint2* ih;
        int ks, nb, l, ldn;
        if (idx < 8192) {
            int j = idx;
            ks = j >> 10; nb = (j >> 5) & 31; l = j & 31;
            W = W1; ih = g_w1h; ldn = 256;
        } else {
            int j = idx - 8192;
            ks = j >> 9; nb = (j >> 5) & 15; l = j & 31;
            W = W2; ih = g_w2h; ldn = 128;
        }
        int k0 = ks * 16 + (l & 3) * 2;
        int nn = nb * 8 + (l >> 2);
        float x00 = W[(size_t)(k0 + 0) * ldn + nn];
        float x01 = W[(size_t)(k0 + 1) * ldn + nn];
        float x10 = W[(size_t)(k0 + 8) * ldn + nn];
        float x11 = W[(size_t)(k0 + 9) * ldn + nn];
        ih[idx & 8191] = make_uint2(pack2h(x00, x01), pack2h(x10, x11));
        return;
    }

    // ---- block 0: pipelined exclusive scan ----
    __shared__ int wsum[32];
    __shared__ int s_carry;
    int lane = tid & 31, wid = tid >> 5;
    if (tid == 0) s_carry = 0;
    int nIter = (n + 1023) >> 10;
    int idx = tid;
    int v = (idx < n) ? g_cnt[idx] : 0;      // prime the pipeline
    __syncthreads();
    for (int it = 0; it < nIter; ++it) {
        int nidx = idx + 1024;
        int vnext = (it + 1 < nIter && nidx < n) ? g_cnt[nidx] : 0;  // prefetch
        int x = v;
        #pragma unroll
        for (int o = 1; o < 32; o <<= 1) {
            int u = __shfl_up_sync(0xffffffffu, x, o);
            if (lane >= o) x += u;
        }
        if (lane == 31) wsum[wid] = x;
        __syncthreads();
        if (wid == 0) {
            int w = wsum[lane];
            #pragma unroll
            for (int o = 1; o < 32; o <<= 1) {
                int u = __shfl_up_sync(0xffffffffu, w, o);
                if (lane >= o) w += u;
            }
            wsum[lane] = w;
        }
        __syncthreads();
        int carry = s_carry;
        int excl = x - v + (wid > 0 ? wsum[wid - 1] : 0) + carry;
        if (idx < n) { g_rs[idx] = excl; g_cur[idx] = excl; g_cnt[idx] = 0; }
        __syncthreads();
        if (tid == 0) s_carry = carry + wsum[31];
        __syncthreads();
        idx = nidx; v = vnext;
    }
    if (tid == 0) g_rs[n] = s_carry;
}

// ---------------- K2: scatter edges by dst ----------------
__global__ void k_scatter(const int* __restrict__ src, const int* __restrict__ dst, int e)
{
    int i = blockIdx.x * blockDim.x + threadIdx.x;
    if (i >= e) return;
    int d = dst[i];
    int s = __ldcs(&src[i]);
    int p = atomicAdd(&g_cur[d], 1);
    g_edges[p] = make_int2(s, i);
}

// ---------------- K3: one-pass softmax aggregation (warp per dst node) ----------------
// 8-edge unroll: 8 edge records staged, then 16 wide gathers in flight.
#define EDGE_ACC(a, hv)                                               \
    {                                                                 \
        float m0 = fmaxf(a.x + hv.x, 0.f) + 1e-7f;                    \
        float m1 = fmaxf(a.y + hv.y, 0.f) + 1e-7f;                    \
        float m2 = fmaxf(a.z + hv.z, 0.f) + 1e-7f;                    \
        float m3 = fmaxf(a.w + hv.w, 0.f) + 1e-7f;                    \
        float e0 = __expf(m0 * t);                                    \
        float e1 = __expf(m1 * t);                                    \
        float e2 = __expf(m2 * t);                                    \
        float e3 = __expf(m3 * t);                                    \
        S.x += e0; P.x = fmaf(m0, e0, P.x);                           \
        S.y += e1; P.y = fmaf(m1, e1, P.y);                           \
        S.z += e2; P.z = fmaf(m2, e2, P.z);                           \
        S.w += e3; P.w = fmaf(m3, e3, P.w);                           \
    }

__global__ void __launch_bounds__(512) k_agg(const float4* __restrict__ ea,
                                             const float* __restrict__ tp, int n)
{
    int warp = (blockIdx.x * blockDim.x + threadIdx.x) >> 5;
    int lane = threadIdx.x & 31;
    if (warp >= n) return;
    float t = __ldg(tp);
    int s0 = g_rs[warp], s1 = g_rs[warp + 1];
    const uint2* hn2 = (const uint2*)g_hn;
    float4 S = make_float4(0.f, 0.f, 0.f, 0.f);
    float4 P = make_float4(0.f, 0.f, 0.f, 0.f);

    int i = s0;
    for (; i + 8 <= s1; i += 8) {
        int2 q[8];
        #pragma unroll
        for (int j = 0; j < 8; ++j) q[j] = __ldcs(&g_edges[i + j]);
        float4 a[8];
        uint2  g[8];
        #pragma unroll
        for (int j = 0; j < 8; ++j) {
            a[j] = __ldcs(&ea[(size_t)q[j].y * HV + lane]);
            g[j] = __ldg (&hn2[(size_t)q[j].x * 32 + lane]);
        }
        #pragma unroll
        for (int j = 0; j < 8; ++j) {
            float4 hv = unpack4h(g[j]);
            EDGE_ACC(a[j], hv);
        }
    }
    for (; i + 4 <= s1; i += 4) {
        int2 q0 = __ldcs(&g_edges[i + 0]);
        int2 q1 = __ldcs(&g_edges[i + 1]);
        int2 q2 = __ldcs(&g_edges[i + 2]);
        int2 q3 = __ldcs(&g_edges[i + 3]);
        float4 a0 = __ldcs(&ea[(size_t)q0.y * HV + lane]);
        uint2  g0 = __ldg (&hn2[(size_t)q0.x * 32 + lane]);
        float4 a1 = __ldcs(&ea[(size_t)q1.y * HV + lane]);
        uint2  g1 = __ldg (&hn2[(size_t)q1.x * 32 + lane]);
        float4 a2 = __ldcs(&ea[(size_t)q2.y * HV + lane]);
        uint2  g2 = __ldg (&hn2[(size_t)q2.x * 32 + lane]);
        float4 a3 = __ldcs(&ea[(size_t)q3.y * HV + lane]);
        uint2  g3 = __ldg (&hn2[(size_t)q3.x * 32 + lane]);
        float4 h0 = unpack4h(g0);
        float4 h1 = unpack4h(g1);
        float4 h2 = unpack4h(g2);
        float4 h3 = unpack4h(g3);
        EDGE_ACC(a0, h0);
        EDGE_ACC(a1, h1);
        EDGE_ACC(a2, h2);
        EDGE_ACC(a3, h3);
    }
    for (; i < s1; ++i) {
        int2 q = __ldcs(&g_edges[i]);
        float4 a  = __ldcs(&ea[(size_t)q.y * HV + lane]);
        float4 hv = unpack4h(__ldg(&hn2[(size_t)q.x * 32 + lane]));
        EDGE_ACC(a, hv);
    }

    float4 hd = unpack4h(hn2[(size_t)warp * 32 + lane]);
    float ux = P.x / (S.x + 1e-16f) + hd.x;
    float uy = P.y / (S.y + 1e-16f) + hd.y;
    float uz = P.z / (S.z + 1e-16f) + hd.z;
    float uw = P.w / (S.w + 1e-16f) + hd.w;
    ((uint2*)g_u)[warp * 32 + lane] = make_uint2(pack2h(ux, uy), pack2h(uz, uw));
}

// ---------------- K5: GEMM1 via mma.sync  y1 = u @ W1 + b1  (+ LN stat atomics) ----------------
// 304 CTAs = 2/SM; CTA owns a 128-col half (32KB weights); u read as ready fp16 fragments.
#define SMEM_MMA1 (32768 + 512)
__global__ void __launch_bounds__(256, 2) k_mma1(const float* __restrict__ b1,
                                                 int n, int nstrips)
{
    extern __shared__ char smem[];
    uint2* sWh  = (uint2*)smem;             // 4096 (32KB): 8 ks x 16 nb x 32 lanes
    float* s_b1 = (float*)(smem + 32768);   // 128
    int tid = threadIdx.x, wid = tid >> 5, lane = tid & 31;
    int half = blockIdx.x & 1, slot = blockIdx.x >> 1;

    for (int i = tid; i < 4096; i += 256) {
        int ks = i >> 9, rem = i & 511;
        sWh[i] = g_w1h[ks * 1024 + half * 512 + rem];
    }
    if (tid < 128) s_b1[tid] = b1[half * 128 + tid];
    __syncthreads();

    int g = lane >> 2, t = lane & 3;
    int nwarps = 152 * 8;
    for (int strip = slot * 8 + wid; strip < nstrips; strip += nwarps) {
        int rg0 = strip * 16 + g;
        int rg1 = rg0 + 8;
        const uint32_t* u0 = g_u + (size_t)rg0 * 64;   // fp16 row: 64 uint32
        const uint32_t* u1 = g_u + (size_t)rg1 * 64;
        float acc[16][4];
        #pragma unroll
        for (int nb = 0; nb < 16; ++nb) {
            float bx = s_b1[nb * 8 + t * 2];
            float by = s_b1[nb * 8 + t * 2 + 1];
            acc[nb][0] = bx; acc[nb][1] = by;
            acc[nb][2] = bx; acc[nb][3] = by;
        }
        #pragma unroll
        for (int ks = 0; ks < 8; ++ks) {
            uint32_t ah[4];
            ah[0] = u0[ks * 8 + t];
            ah[1] = u1[ks * 8 + t];
            ah[2] = u0[ks * 8 + t + 4];
            ah[3] = u1[ks * 8 + t + 4];
            const uint2* wh = sWh + ks * 512 + lane;
            #pragma unroll
            for (int nb = 0; nb < 16; ++nb) {
                uint2 bh = wh[nb * 32];
                mma_f32acc(acc[nb], ah, bh.x, bh.y);
            }
        }

        // ---- LN partial stats over this half's 128 cols; quad-reduce; 2 atomics/row ----
        float sA = 0.f, s2A = 0.f, sB = 0.f, s2B = 0.f;
        #pragma unroll
        for (int nb = 0; nb < 16; ++nb) {
            sA += acc[nb][0] + acc[nb][1];
            s2A = fmaf(acc[nb][0], acc[nb][0], fmaf(acc[nb][1], acc[nb][1], s2A));
            sB += acc[nb][2] + acc[nb][3];
            s2B = fmaf(acc[nb][2], acc[nb][2], fmaf(acc[nb][3], acc[nb][3], s2B));
        }
        #pragma unroll
        for (int o = 1; o < 4; o <<= 1) {
            sA  += __shfl_xor_sync(0xffffffffu, sA, o);
            s2A += __shfl_xor_sync(0xffffffffu, s2A, o);
            sB  += __shfl_xor_sync(0xffffffffu, sB, o);
            s2B += __shfl_xor_sync(0xffffffffu, s2B, o);
        }
        if (t == 0) {
            if (rg0 < n) {
                atomicAdd(&g_lnstat[rg0].x, sA);
                atomicAdd(&g_lnstat[rg0].y, s2A);
            }
            if (rg1 < n) {
                atomicAdd(&g_lnstat[rg1].x, sB);
                atomicAdd(&g_lnstat[rg1].y, s2B);
            }
        }

        // ---- store y1 as fp16 (one uint32 per nb per row) ----
        #pragma unroll
        for (int nb = 0; nb < 16; ++nb) {
            int ci = half * 64 + nb * 4 + t;      // uint32 index within row of 128
            if (rg0 < n) g_y1[(size_t)rg0 * 128 + ci] = pack2h(acc[nb][0], acc[nb][1]);
            if (rg1 < n) g_y1[(size_t)rg1 * 128 + ci] = pack2h(acc[nb][2], acc[nb][3]);
        }
    }
}

// ---------------- K6: GEMM2 via mma.sync  out = relu(LN(y1)) @ W2 + b2 + h ----------------
// 304 CTAs = 2/SM; CTA owns a 64-col half; LN mean/scale from g_lnstat; y1 read as fp16.
#define SMEM_MMA2 (32768 + 2304)
__global__ void __launch_bounds__(256, 2) k_mma2(const float* __restrict__ b2,
                                                 const float* __restrict__ lnw,
                                                 const float* __restrict__ lnb,
                                                 const float* __restrict__ hres,
                                                 float* __restrict__ out,
                                                 int n, int nstrips)
{
    extern __shared__ char smem[];
    uint2* sWh   = (uint2*)smem;                     // 4096 (32KB): 16 ks x 8 nb x 32 lanes
    float* s_lnw = (float*)(smem + 32768);           // 256
    float* s_lnb = (float*)(smem + 32768 + 1024);    // 256
    float* s_b2  = (float*)(smem + 32768 + 2048);    // 64
    int tid = threadIdx.x, wid = tid >> 5, lane = tid & 31;
    int half = blockIdx.x & 1, slot = blockIdx.x >> 1;

    for (int i = tid; i < 4096; i += 256) {
        int ks = i >> 8, rem = i & 255;
        sWh[i] = g_w2h[ks * 512 + half * 256 + rem];
    }
    if (tid < 256) { s_lnw[tid] = lnw[tid]; s_lnb[tid] = lnb[tid]; }
    if (tid < 64) s_b2[tid] = b2[half * 64 + tid];
    __syncthreads();

    int g = lane >> 2, t = lane & 3;
    int nwarps = 152 * 8;
    for (int strip = slot * 8 + wid; strip < nstrips; strip += nwarps) {
        int rg0 = strip * 16 + g, rg1 = rg0 + 8;

        float2 stA = (rg0 < n) ? g_lnstat[rg0] : make_float2(0.f, 0.f);
        float2 stB = (rg1 < n) ? g_lnstat[rg1] : make_float2(0.f, 0.f);
        float meanA = stA.x * (1.f / 256.f);
        float varA  = fmaxf(stA.y * (1.f / 256.f) - meanA * meanA, 0.f);
        float scaleA = rsqrtf(varA + 1e-5f);
        float meanB = stB.x * (1.f / 256.f);
        float varB  = fmaxf(stB.y * (1.f / 256.f) - meanB * meanB, 0.f);
        float scaleB = rsqrtf(varB + 1e-5f);

        const uint32_t* y0 = g_y1 + (size_t)rg0 * 128;
        const uint32_t* y1 = g_y1 + (size_t)rg1 * 128;
        float acc[8][4];
        #pragma unroll
        for (int nb = 0; nb < 8; ++nb) {
            acc[nb][0] = 0.f; acc[nb][1] = 0.f; acc[nb][2] = 0.f; acc[nb][3] = 0.f;
        }
        #pragma unroll
        for (int ks = 0; ks < 16; ++ks) {
            int k0 = ks * 16 + t * 2;
            float2 v00 = unpack2h(y0[ks * 8 + t]);
            float2 v01 = unpack2h(y0[ks * 8 + t + 4]);
            float2 v10 = unpack2h(y1[ks * 8 + t]);
            float2 v11 = unpack2h(y1[ks * 8 + t + 4]);
            float2 w0 = *(const float2*)(s_lnw + k0);
            float2 w1 = *(const float2*)(s_lnw + k0 + 8);
            float2 z0 = *(const float2*)(s_lnb + k0);
            float2 z1 = *(const float2*)(s_lnb + k0 + 8);
            float x00 = fmaxf((v00.x - meanA) * scaleA * w0.x + z0.x, 0.f);
            float x01 = fmaxf((v00.y - meanA) * scaleA * w0.y + z0.y, 0.f);
            float x02 = fmaxf((v01.x - meanA) * scaleA * w1.x + z1.x, 0.f);
            float x03 = fmaxf((v01.y - meanA) * scaleA * w1.y + z1.y, 0.f);
            float x10 = fmaxf((v10.x - meanB) * scaleB * w0.x + z0.x, 0.f);
            float x11 = fmaxf((v10.y - meanB) * scaleB * w0.y + z0.y, 0.f);
            float x12 = fmaxf((v11.x - meanB) * scaleB * w1.x + z1.x, 0.f);
            float x13 = fmaxf((v11.y - meanB) * scaleB * w1.y + z1.y, 0.f);
            uint32_t ah[4];
            ah[0] = pack2h(x00, x01);
            ah[1] = pack2h(x10, x11);
            ah[2] = pack2h(x02, x03);
            ah[3] = pack2h(x12, x13);
            const uint2* wh = sWh + ks * 256 + lane;
            #pragma unroll
            for (int nb = 0; nb < 8; ++nb) {
                uint2 bh = wh[nb * 32];
                mma_f32acc(acc[nb], ah, bh.x, bh.y);
            }
        }
        #pragma unroll
        for (int nb = 0; nb < 8; ++nb) {
            int col = half * 64 + nb * 8 + t * 2;
            float2 bb = *(const float2*)(s_b2 + nb * 8 + t * 2);
            if (rg0 < n) {
                float2 hv = *(const float2*)(hres + (size_t)rg0 * 128 + col);
                *(float2*)(out + (size_t)rg0 * 128 + col) =
                    make_float2(acc[nb][0] + bb.x + hv.x, acc[nb][1] + bb.y + hv.y);
            }
            if (rg1 < n) {
                float2 hv = *(const float2*)(hres + (size_t)rg1 * 128 + col);
                *(float2*)(out + (size_t)rg1 * 128 + col) =
                    make_float2(acc[nb][2] + bb.x + hv.x, acc[nb][3] + bb.y + hv.y);
            }
        }
    }
}

// ---------------- launch ----------------
extern "C" void kernel_launch(void* const* d_in, const int* in_sizes, int n_in,
                              void* d_out, int out_size)
{
    const float* h   = (const float*)d_in[0];
    const int*   ei  = (const int*)  d_in[1];
    const float* ea  = (const float*)d_in[2];
    const float* bw  = (const float*)d_in[3];
    const float* bb  = (const float*)d_in[4];
    const float* bm  = (const float*)d_in[5];
    const float* bv  = (const float*)d_in[6];
    const float* tp  = (const float*)d_in[7];
    const float* W1  = (const float*)d_in[8];
    const float* b1  = (const float*)d_in[9];
    const float* lnw = (const float*)d_in[10];
    const float* lnb = (const float*)d_in[11];
    const float* W2  = (const float*)d_in[12];
    const float* b2  = (const float*)d_in[13];

    int n = in_sizes[0] / HF;
    int e = in_sizes[2] / HF;
    const int* src = ei;
    const int* dst = ei + e;
    int nstrips = (n + 15) / 16;

    cudaFuncSetAttribute(k_mma1, cudaFuncAttributeMaxDynamicSharedMemorySize, SMEM_MMA1);
    cudaFuncSetAttribute(k_mma2, cudaFuncAttributeMaxDynamicSharedMemorySize, SMEM_MMA2);

    k_hn_hist<<<(n * HV + 255) / 256, 256>>>((const float4*)h, (const float4*)bw,
                                             (const float4*)bb, (const float4*)bm,
                                             (const float4*)bv, dst, n, e);
    k_scan_prepw<<<17, 1024>>>(n, W1, W2);
    k_scatter<<<(e + 255) / 256, 256>>>(src, dst, e);
    k_agg<<<(n + 15) / 16, 512>>>((const float4*)ea, tp, n);    // <- ncu capture lands here
    k_mma1<<<304, 256, SMEM_MMA1>>>(b1, n, nstrips);
    k_mma2<<<304, 256, SMEM_MMA2>>>(b2, lnw, lnb, h, (float*)d_out, n, nstrips);
}